// round 1
// baseline (speedup 1.0000x reference)
#include <cuda_runtime.h>
#include <cuda_bf16.h>
#include <math.h>

// Problem constants
#define BB 8
#define SS 512
#define HH 768
#define NHH 12
#define DHH 64
#define LL 12
#define VV 21128
#define FFF 3072
#define PLEN 128
#define NTOK (BB*SS)          // 4096
#define NVALID_PER_B (SS-PLEN) // 384
#define NVALID (BB*NVALID_PER_B) // 3072

// ---------------- scratch (device globals; no allocations allowed) ----------
__device__ float g_h[NTOK*HH];
__device__ float g_q[NTOK*HH];
__device__ float g_k[NTOK*HH];
__device__ float g_v[NTOK*HH];
__device__ float g_ctx[NTOK*HH];
__device__ float g_tmp[NTOK*HH];
__device__ float g_ffn[NTOK*FFF];
__device__ float g_scores[(size_t)BB*NHH*SS*SS];      // 96*512*512 = 25.2M floats
__device__ float g_logits[(size_t)NVALID*VV];         // 3072*21128
__device__ float g_loss_sum;

// ---------------- small helpers --------------------------------------------
__device__ __forceinline__ float warpSum(float v){
  #pragma unroll
  for (int o=16;o;o>>=1) v += __shfl_xor_sync(0xffffffffu, v, o);
  return v;
}
__device__ __forceinline__ float warpMax(float v){
  #pragma unroll
  for (int o=16;o;o>>=1) v = fmaxf(v, __shfl_xor_sync(0xffffffffu, v, o));
  return v;
}
template<int NW>
__device__ __forceinline__ float blockSum(float v){
  __shared__ float sh[NW];
  __syncthreads();
  v = warpSum(v);
  if ((threadIdx.x & 31)==0) sh[threadIdx.x>>5] = v;
  __syncthreads();
  float r = 0.f;
  #pragma unroll
  for (int i=0;i<NW;i++) r += sh[i];
  return r;
}
template<int NW>
__device__ __forceinline__ float blockMax(float v){
  __shared__ float sh[NW];
  __syncthreads();
  v = warpMax(v);
  if ((threadIdx.x & 31)==0) sh[threadIdx.x>>5] = v;
  __syncthreads();
  float r = -3.4e38f;
  #pragma unroll
  for (int i=0;i<NW;i++) r = fmaxf(r, sh[i]);
  return r;
}
__device__ __forceinline__ float gelu_exact(float x){
  return 0.5f * x * (1.0f + erff(x * 0.70710678118654752f));
}

// ---------------- generic GEMM: C = A @ op(B) + bias, opt GELU -------------
// A: [M,K] row-major (lda). B: NN -> [K,N] (ldb); NT -> [N,K] (ldb), C=A@B^T.
// Batch over blockIdx.z with two-level offsets: z -> (zo = z/batchInner, zi).
// Packed f32x2 FMA inner loop (Blackwell FFMA2, PTX-only path).
#define BKK 16
template<int BM, int BN, int TM, int TN, bool TRANSB, int ACT>
__global__ __launch_bounds__(256) void gemm_kernel(
    const float* __restrict__ Ag, const float* __restrict__ Bg,
    const float* __restrict__ bias, float* __restrict__ Cg,
    int M, int N, int K, int lda, int ldb, int ldc,
    int batchInner,
    long long sA1, long long sA2, long long sB1, long long sB2,
    long long sC1, long long sC2)
{
  int z  = blockIdx.z;
  int zo = z / batchInner;
  int zi = z - zo * batchInner;
  const float* A  = Ag + zo*sA1 + zi*sA2;
  const float* Bp = Bg + zo*sB1 + zi*sB2;
  float*       C  = Cg + zo*sC1 + zi*sC2;

  __shared__ __align__(16) float As[BKK][BM+2];
  __shared__ __align__(16) float Bs[BKK][BN+2];

  const int tid = threadIdx.x;
  const int tx = tid & 15;        // 16 col-groups
  const int ty = tid >> 4;        // 16 row-groups
  const int m0 = blockIdx.y * BM;
  const int n0 = blockIdx.x * BN;

  constexpr int NP = TN/2;
  unsigned long long acc[TM][NP];
  #pragma unroll
  for (int i=0;i<TM;i++)
    #pragma unroll
    for (int j=0;j<NP;j++) acc[i][j] = 0ULL;

  constexpr int AE = BM*BKK/256;
  constexpr int BE = BN*BKK/256;

  for (int k0 = 0; k0 < K; k0 += BKK) {
    // A tile -> As[kk][m]  (coalesced along k)
    #pragma unroll
    for (int i=0;i<AE;i++){
      int idx = i*256 + tid;
      int m  = idx >> 4;
      int kk = idx & 15;
      As[kk][m] = A[(size_t)(m0+m)*lda + (k0+kk)];
    }
    // B tile -> Bs[kk][n]
    if (TRANSB) {
      #pragma unroll
      for (int i=0;i<BE;i++){
        int idx = i*256 + tid;
        int n  = idx >> 4;
        int kk = idx & 15;
        float vv = 0.f;
        if (n0+n < N) vv = Bp[(size_t)(n0+n)*ldb + (k0+kk)];
        Bs[kk][n] = vv;
      }
    } else {
      #pragma unroll
      for (int i=0;i<BE;i++){
        int idx = i*256 + tid;
        int kk = idx / BN;
        int n  = idx - kk*BN;
        float vv = 0.f;
        if (n0+n < N) vv = Bp[(size_t)(k0+kk)*ldb + (n0+n)];
        Bs[kk][n] = vv;
      }
    }
    __syncthreads();

    #pragma unroll
    for (int kk=0; kk<BKK; kk++){
      unsigned long long bv[NP];
      #pragma unroll
      for (int j=0;j<NP;j++)
        bv[j] = *reinterpret_cast<const unsigned long long*>(&Bs[kk][tx*TN + 2*j]);
      #pragma unroll
      for (int i=0;i<TM;i++){
        float a = As[kk][ty*TM + i];
        unsigned long long ap;
        asm("mov.b64 %0, {%1, %1};" : "=l"(ap) : "r"(__float_as_uint(a)));
        #pragma unroll
        for (int j=0;j<NP;j++)
          asm("fma.rn.f32x2 %0, %1, %2, %0;" : "+l"(acc[i][j]) : "l"(ap), "l"(bv[j]));
      }
    }
    __syncthreads();
  }

  // epilogue
  #pragma unroll
  for (int i=0;i<TM;i++){
    int m = m0 + ty*TM + i;
    #pragma unroll
    for (int j=0;j<NP;j++){
      int n = n0 + tx*TN + 2*j;
      float lo = __uint_as_float((unsigned)(acc[i][j] & 0xffffffffULL));
      float hi = __uint_as_float((unsigned)(acc[i][j] >> 32));
      if (bias){
        if (n   < N) lo += bias[n];
        if (n+1 < N) hi += bias[n+1];
      }
      if (ACT == 1){ lo = gelu_exact(lo); hi = gelu_exact(hi); }
      if (n   < N) C[(size_t)m*ldc + n]   = lo;
      if (n+1 < N) C[(size_t)m*ldc + n+1] = hi;
    }
  }
}

// ---------------- embeddings + LN ------------------------------------------
__global__ void embed_ln_kernel(const int* __restrict__ ids,
                                const float* __restrict__ we,
                                const float* __restrict__ pe,
                                const float* __restrict__ te,
                                const float* __restrict__ g,
                                const float* __restrict__ b)
{
  int t = blockIdx.x;
  int s = t & (SS-1);
  int id = ids[t];
  const float* wrow = we + (size_t)id*HH;
  const float* prow = pe + (size_t)s*HH;
  float x[3];
  float lsum = 0.f;
  #pragma unroll
  for (int i=0;i<3;i++){
    int c = threadIdx.x + i*256;
    x[i] = wrow[c] + prow[c] + te[c];
    lsum += x[i];
  }
  float mean = blockSum<8>(lsum) * (1.0f/HH);
  float ls2 = 0.f;
  #pragma unroll
  for (int i=0;i<3;i++){ x[i] -= mean; ls2 += x[i]*x[i]; }
  float var = blockSum<8>(ls2) * (1.0f/HH);
  float inv = rsqrtf(var + 1e-12f);
  #pragma unroll
  for (int i=0;i<3;i++){
    int c = threadIdx.x + i*256;
    g_h[(size_t)t*HH + c] = x[i]*inv*g[c] + b[c];
  }
}

// ---------------- residual + LN (in place on g_h) --------------------------
__global__ void resln_kernel(const float* __restrict__ r,   // added term
                             const float* __restrict__ g,
                             const float* __restrict__ b)
{
  int t = blockIdx.x;
  float x[3];
  float lsum = 0.f;
  #pragma unroll
  for (int i=0;i<3;i++){
    int c = threadIdx.x + i*256;
    x[i] = g_h[(size_t)t*HH + c] + r[(size_t)t*HH + c];
    lsum += x[i];
  }
  float mean = blockSum<8>(lsum) * (1.0f/HH);
  float ls2 = 0.f;
  #pragma unroll
  for (int i=0;i<3;i++){ x[i] -= mean; ls2 += x[i]*x[i]; }
  float var = blockSum<8>(ls2) * (1.0f/HH);
  float inv = rsqrtf(var + 1e-12f);
  #pragma unroll
  for (int i=0;i<3;i++){
    int c = threadIdx.x + i*256;
    g_h[(size_t)t*HH + c] = x[i]*inv*g[c] + b[c];
  }
}

// ---------------- masked softmax over scores (in place) --------------------
// grid: (S, B*NH), 128 threads. mask: key j visible iff j<PLEN || j<=query s.
__global__ void softmax_kernel()
{
  int z = blockIdx.y;
  int s = blockIdx.x;
  float* row = g_scores + ((size_t)z*SS + s)*SS;
  float x[4];
  float mx = -3.4e38f;
  #pragma unroll
  for (int i=0;i<4;i++){
    int j = threadIdx.x + i*128;
    float v = row[j] * 0.125f;                 // 1/sqrt(64)
    if (!(j < PLEN || j <= s)) v += -1e9f;
    x[i] = v;
    mx = fmaxf(mx, v);
  }
  mx = blockMax<4>(mx);
  float ls = 0.f;
  #pragma unroll
  for (int i=0;i<4;i++){ x[i] = __expf(x[i] - mx); ls += x[i]; }
  float sum = blockSum<4>(ls);
  float inv = 1.0f / sum;
  #pragma unroll
  for (int i=0;i<4;i++){
    int j = threadIdx.x + i*128;
    row[j] = x[i] * inv;
  }
}

// ---------------- cross entropy over valid rows ----------------------------
__global__ void zero_loss_kernel(){ g_loss_sum = 0.f; }

__global__ void ce_kernel(const int* __restrict__ labels)
{
  int r = blockIdx.x;                 // 0..NVALID-1
  int bb = r / NVALID_PER_B;
  int s  = PLEN + (r - bb*NVALID_PER_B);
  const float* row = g_logits + (size_t)r*VV;
  int lab = labels[bb*SS + s];

  float mx = -3.4e38f;
  for (int j = threadIdx.x; j < VV; j += 256) mx = fmaxf(mx, row[j]);
  mx = blockMax<8>(mx);
  float ls = 0.f;
  for (int j = threadIdx.x; j < VV; j += 256) ls += __expf(row[j] - mx);
  float sum = blockSum<8>(ls);
  if (threadIdx.x == 0){
    float nll = (logf(sum) + mx) - row[lab];
    atomicAdd(&g_loss_sum, nll);
  }
}

__global__ void finalize_kernel(float* out){
  out[0] = g_loss_sum * (1.0f/(float)NVALID);
}

// ---------------- host orchestration ---------------------------------------
static void launch_gemm_nn_128(const float* A, const float* B, const float* bias,
                               float* C, int M, int N, int K,
                               int lda, int ldb, int ldc, int act)
{
  dim3 grid((N+127)/128, M/128, 1);
  if (act)
    gemm_kernel<128,128,8,8,false,1><<<grid,256>>>(A,B,bias,C,M,N,K,lda,ldb,ldc,1,0,0,0,0,0,0);
  else
    gemm_kernel<128,128,8,8,false,0><<<grid,256>>>(A,B,bias,C,M,N,K,lda,ldb,ldc,1,0,0,0,0,0,0);
}

extern "C" void kernel_launch(void* const* d_in, const int* in_sizes, int n_in,
                              void* d_out, int out_size)
{
  const int*   input_ids = (const int*)  d_in[0];
  const int*   labels    = (const int*)  d_in[1];
  const float* word_emb  = (const float*)d_in[2];
  const float* pos_emb   = (const float*)d_in[3];
  const float* type_emb  = (const float*)d_in[4];
  const float* eg        = (const float*)d_in[5];
  const float* eb        = (const float*)d_in[6];
  const float* Wq = (const float*)d_in[7];  const float* bq = (const float*)d_in[8];
  const float* Wk = (const float*)d_in[9];  const float* bk = (const float*)d_in[10];
  const float* Wv = (const float*)d_in[11]; const float* bv = (const float*)d_in[12];
  const float* Wo = (const float*)d_in[13]; const float* bo = (const float*)d_in[14];
  const float* ln1g = (const float*)d_in[15]; const float* ln1b = (const float*)d_in[16];
  const float* W1 = (const float*)d_in[17]; const float* bf1 = (const float*)d_in[18];
  const float* W2 = (const float*)d_in[19]; const float* bf2 = (const float*)d_in[20];
  const float* ln2g = (const float*)d_in[21]; const float* ln2b = (const float*)d_in[22];
  const float* Wc = (const float*)d_in[23]; const float* bc = (const float*)d_in[24];
  float* out = (float*)d_out;

  // device-global scratch addresses (query is capture-safe: no stream work)
  float *p_h, *p_q, *p_k, *p_v, *p_ctx, *p_tmp, *p_ffn, *p_sc, *p_lg;
  cudaGetSymbolAddress((void**)&p_h,   g_h);
  cudaGetSymbolAddress((void**)&p_q,   g_q);
  cudaGetSymbolAddress((void**)&p_k,   g_k);
  cudaGetSymbolAddress((void**)&p_v,   g_v);
  cudaGetSymbolAddress((void**)&p_ctx, g_ctx);
  cudaGetSymbolAddress((void**)&p_tmp, g_tmp);
  cudaGetSymbolAddress((void**)&p_ffn, g_ffn);
  cudaGetSymbolAddress((void**)&p_sc,  g_scores);
  cudaGetSymbolAddress((void**)&p_lg,  g_logits);

  zero_loss_kernel<<<1,1>>>();
  embed_ln_kernel<<<NTOK,256>>>(input_ids, word_emb, pos_emb, type_emb, eg, eb);

  const long long HDsq = (long long)HH*HH;
  const long long headStride = (long long)SS*HH;   // batch stride in token space
  const long long scStrideH  = (long long)SS*SS;   // per-head score block
  const long long scStrideB  = (long long)NHH*SS*SS;

  for (int l = 0; l < LL; l++) {
    const float* wq = Wq + (size_t)l*HDsq; const float* bql = bq + (size_t)l*HH;
    const float* wk = Wk + (size_t)l*HDsq; const float* bkl = bk + (size_t)l*HH;
    const float* wv = Wv + (size_t)l*HDsq; const float* bvl = bv + (size_t)l*HH;
    const float* wo = Wo + (size_t)l*HDsq; const float* bol = bo + (size_t)l*HH;
    const float* w1 = W1 + (size_t)l*HH*FFF; const float* b1l = bf1 + (size_t)l*FFF;
    const float* w2 = W2 + (size_t)l*FFF*HH; const float* b2l = bf2 + (size_t)l*HH;

    // QKV projections: [4096,768] @ [768,768] + b
    launch_gemm_nn_128(p_h, wq, bql, p_q, NTOK, HH, HH, HH, HH, HH, 0);
    launch_gemm_nn_128(p_h, wk, bkl, p_k, NTOK, HH, HH, HH, HH, HH, 0);
    launch_gemm_nn_128(p_h, wv, bvl, p_v, NTOK, HH, HH, HH, HH, HH, 0);

    // scores[b,h,s,t] = q . k  (NT), batched over z = b*NH + h
    {
      dim3 grid(SS/128, SS/128, BB*NHH);
      gemm_kernel<128,128,8,8,true,0><<<grid,256>>>(
        p_q, p_k, nullptr, p_sc,
        SS, SS, DHH, HH, HH, SS,
        NHH,
        headStride, (long long)DHH,      // A: b*S*H + h*DH
        headStride, (long long)DHH,      // B: same
        scStrideB,  scStrideH);          // C: (b*NH+h)*S*S
    }

    softmax_kernel<<<dim3(SS, BB*NHH), 128>>>();

    // ctx[b,s,h*DH+d] = attn @ v  (NN), M=512,N=64,K=512
    {
      dim3 grid(1, SS/128, BB*NHH);
      gemm_kernel<128,64,8,4,false,0><<<grid,256>>>(
        p_sc, p_v, nullptr, p_ctx,
        SS, DHH, SS, SS, HH, HH,
        NHH,
        scStrideB,  scStrideH,           // A: scores
        headStride, (long long)DHH,      // B: v
        headStride, (long long)DHH);     // C: ctx at col h*DH
    }

    // output proj + residual LN
    launch_gemm_nn_128(p_ctx, wo, bol, p_tmp, NTOK, HH, HH, HH, HH, HH, 0);
    resln_kernel<<<NTOK,256>>>(p_tmp, ln1g + (size_t)l*HH, ln1b + (size_t)l*HH);

    // FFN
    launch_gemm_nn_128(p_h, w1, b1l, p_ffn, NTOK, FFF, HH, HH, FFF, FFF, 1); // fused GELU
    launch_gemm_nn_128(p_ffn, w2, b2l, p_tmp, NTOK, HH, FFF, FFF, HH, HH, 0);
    resln_kernel<<<NTOK,256>>>(p_tmp, ln2g + (size_t)l*HH, ln2b + (size_t)l*HH);
  }

  // logits only for valid tokens: rows s in [128,512) per batch (contiguous!)
  {
    dim3 grid((VV+127)/128, NVALID_PER_B/128, BB);
    gemm_kernel<128,128,8,8,false,0><<<grid,256>>>(
      p_h + (size_t)PLEN*HH, Wc, bc, p_lg,
      NVALID_PER_B, VV, HH, HH, VV, VV,
      1,
      (long long)SS*HH, 0,               // A: + b*S*H
      0, 0,
      (long long)NVALID_PER_B*VV, 0);    // C: + b*384*V
  }

  ce_kernel<<<NVALID,256>>>(labels);
  finalize_kernel<<<1,1>>>(out);
}

// round 3
// speedup vs baseline: 2.1092x; 2.1092x over previous
#include <cuda_runtime.h>
#include <cstdint>
#include <math.h>

// Problem constants
#define BB 8
#define SS 512
#define HH 768
#define NHH 12
#define DHH 64
#define LL 12
#define VV 21128
#define FFF 3072
#define PLEN 128
#define NTOK (BB*SS)
#define NVALID_PER_B (SS-PLEN)
#define NVALID (BB*NVALID_PER_B)

// ---------------- scratch (device globals; no allocations allowed) ----------
__device__ float g_h[NTOK*HH];
__device__ float g_q[NTOK*HH];
__device__ float g_k[NTOK*HH];
__device__ float g_v[NTOK*HH];
__device__ float g_ctx[NTOK*HH];
__device__ float g_tmp[NTOK*HH];
__device__ float g_ffn[NTOK*FFF];
__device__ float g_scores[(size_t)BB*NHH*SS*SS];
__device__ float g_logits[(size_t)NVALID*VV];
__device__ float g_loss_sum;

// ---------------- helpers ----------------------------------------------------
__device__ __forceinline__ float warpSum(float v){
  #pragma unroll
  for (int o=16;o;o>>=1) v += __shfl_xor_sync(0xffffffffu, v, o);
  return v;
}
__device__ __forceinline__ float warpMax(float v){
  #pragma unroll
  for (int o=16;o;o>>=1) v = fmaxf(v, __shfl_xor_sync(0xffffffffu, v, o));
  return v;
}
template<int NW>
__device__ __forceinline__ float blockSum(float v){
  __shared__ float sh[NW];
  __syncthreads();
  v = warpSum(v);
  if ((threadIdx.x & 31)==0) sh[threadIdx.x>>5] = v;
  __syncthreads();
  float r = 0.f;
  #pragma unroll
  for (int i=0;i<NW;i++) r += sh[i];
  return r;
}
template<int NW>
__device__ __forceinline__ float blockMax(float v){
  __shared__ float sh[NW];
  __syncthreads();
  v = warpMax(v);
  if ((threadIdx.x & 31)==0) sh[threadIdx.x>>5] = v;
  __syncthreads();
  float r = -3.4e38f;
  #pragma unroll
  for (int i=0;i<NW;i++) r = fmaxf(r, sh[i]);
  return r;
}
__device__ __forceinline__ float gelu_exact(float x){
  return 0.5f * x * (1.0f + erff(x * 0.70710678118654752f));
}

__device__ __forceinline__ uint32_t smem_u32(const void* p){
  uint32_t a;
  asm("{ .reg .u64 t; cvta.to.shared.u64 t, %1; cvt.u32.u64 %0, t; }" : "=r"(a) : "l"(p));
  return a;
}
__device__ __forceinline__ void cp16(uint32_t dst, const void* src){
  asm volatile("cp.async.ca.shared.global [%0], [%1], 16;" :: "r"(dst), "l"(src));
}
__device__ __forceinline__ void cp16p(uint32_t dst, const void* src, bool valid){
  int sz = valid ? 16 : 0;
  asm volatile("cp.async.ca.shared.global [%0], [%1], 16, %2;"
               :: "r"(dst), "l"(src), "r"(sz));
}
__device__ __forceinline__ void cp_commit(){
  asm volatile("cp.async.commit_group;" ::: "memory");
}
template<int N>
__device__ __forceinline__ void cp_wait(){
  asm volatile("cp.async.wait_group %0;" :: "n"(N) : "memory");
}

// split fp32 -> tf32 hi (exact mask) + lo (exact remainder)
__device__ __forceinline__ void split_tf32(float x, uint32_t& hi, uint32_t& lo){
  uint32_t xb = __float_as_uint(x);
  hi = xb & 0xffffe000u;
  lo = __float_as_uint(x - __uint_as_float(hi));
}

__device__ __forceinline__ void mma_tf32(float* d, const uint32_t* a, const uint32_t* b){
  asm volatile(
    "mma.sync.aligned.m16n8k8.row.col.f32.tf32.tf32.f32 "
    "{%0,%1,%2,%3}, {%4,%5,%6,%7}, {%8,%9}, {%0,%1,%2,%3};\n"
    : "+f"(d[0]), "+f"(d[1]), "+f"(d[2]), "+f"(d[3])
    : "r"(a[0]), "r"(a[1]), "r"(a[2]), "r"(a[3]), "r"(b[0]), "r"(b[1]));
}

// ---------------- 3xTF32 mma.sync GEMM ---------------------------------------
// C[M,N] = A[M,K] @ op(B) (+bias)(+GELU). TRANSB: B is [N,K] (NT, C=A@B^T);
// else B is [K,N] (NN). BM=128 fixed, BK=16, cp.async double buffered.
#define BKc 16

template<int BN, bool TRANSB, int ACT>
__global__ __launch_bounds__(256) void gemm_mma(
    const float* __restrict__ Ag, const float* __restrict__ Bg,
    const float* __restrict__ bias, float* __restrict__ Cg,
    int M, int N, int K, int lda, int ldb, int ldc,
    int batchInner,
    long long sA1, long long sA2, long long sB1, long long sB2,
    long long sC1, long long sC2)
{
  constexpr int BM = 128;
  constexpr int WARPS_M = (BN==128) ? 2 : 4;
  constexpr int WARPS_N = 8 / WARPS_M;
  constexpr int WM = BM / WARPS_M;       // 64 or 32
  constexpr int WN = BN / WARPS_N;       // 32
  constexpr int MF = WM / 16;            // 4 or 2
  constexpr int NF = WN / 8;             // 4

  __shared__ float As[2][BM][BKc+4];     // raw fp32, row-major [m][k]
  __shared__ float Bs[2][BKc][BN+8];     // raw fp32, [k][n]

  const int tid  = threadIdx.x;
  const int wid  = tid >> 5;
  const int lane = tid & 31;
  const int grp  = lane >> 2;            // 0..7
  const int tig  = lane & 3;             // 0..3

  const int z  = blockIdx.z;
  const int zo = z / batchInner;
  const int zi = z - zo * batchInner;
  const float* A  = Ag + zo*sA1 + zi*sA2;
  const float* Bp = Bg + zo*sB1 + zi*sB2;
  float*       C  = Cg + zo*sC1 + zi*sC2;

  const int m0 = blockIdx.y * BM;
  const int n0 = blockIdx.x * BN;
  const int wm = (wid / WARPS_N) * WM;
  const int wn = (wid % WARPS_N) * WN;

  float acc[MF][NF][4];
  #pragma unroll
  for (int i=0;i<MF;i++)
    #pragma unroll
    for (int j=0;j<NF;j++)
      #pragma unroll
      for (int r=0;r<4;r++) acc[i][j][r] = 0.f;

  const int nch = K / BKc;

  // ---- tile loaders ----
  auto loadA = [&](int c, int buf){
    int k0 = c * BKc;
    #pragma unroll
    for (int i=0;i<2;i++){
      int idx = i*256 + tid;
      int row = idx >> 2;                // 0..127
      int kg  = idx & 3;                 // 0..3 (float4 within 16)
      uint32_t dst = smem_u32(&As[buf][row][kg*4]);
      cp16(dst, A + (size_t)(m0+row)*lda + k0 + kg*4);
    }
  };
  auto loadB = [&](int c, int buf){
    int k0 = c * BKc;
    if (TRANSB){
      // B[N,K]; write Bs[k][n] transposed (direct stores; N assumed full tile)
      int n  = tid & 127;
      int hf = tid >> 7;                 // 0/1 -> k-halves of 8
      const float* src = Bp + (size_t)(n0+n)*ldb + k0 + hf*8;
      float4 v0 = *reinterpret_cast<const float4*>(src);
      float4 v1 = *reinterpret_cast<const float4*>(src+4);
      Bs[buf][hf*8+0][n] = v0.x; Bs[buf][hf*8+1][n] = v0.y;
      Bs[buf][hf*8+2][n] = v0.z; Bs[buf][hf*8+3][n] = v0.w;
      Bs[buf][hf*8+4][n] = v1.x; Bs[buf][hf*8+5][n] = v1.y;
      Bs[buf][hf*8+6][n] = v1.z; Bs[buf][hf*8+7][n] = v1.w;
    } else {
      constexpr int NB4 = BKc*BN/4/256;  // float4 per thread (2 or 1)
      #pragma unroll
      for (int i=0;i<NB4;i++){
        int idx = i*256 + tid;
        int k  = idx / (BN/4);
        int ng = idx % (BN/4);
        int gn = n0 + ng*4;
        uint32_t dst = smem_u32(&Bs[buf][k][ng*4]);
        bool valid = (gn < N);
        const float* src = valid ? (Bp + (size_t)(k0+k)*ldb + gn) : Bp;
        cp16p(dst, src, valid);
      }
    }
  };

  // ---- prologue ----
  loadA(0, 0);
  loadB(0, 0);
  cp_commit();

  for (int c = 0; c < nch; c++){
    const int buf = c & 1;
    if (c+1 < nch){
      loadA(c+1, buf^1);
      loadB(c+1, buf^1);
      cp_commit();
      cp_wait<1>();
    } else {
      cp_wait<0>();
    }
    __syncthreads();

    // ---- compute on buf ----
    #pragma unroll
    for (int ks=0; ks<2; ks++){
      const int kc = ks*8;
      uint32_t ah[MF][4], al[MF][4];
      #pragma unroll
      for (int mf=0; mf<MF; mf++){
        int r0 = wm + mf*16 + grp;
        split_tf32(As[buf][r0  ][kc+tig  ], ah[mf][0], al[mf][0]);
        split_tf32(As[buf][r0+8][kc+tig  ], ah[mf][1], al[mf][1]);
        split_tf32(As[buf][r0  ][kc+tig+4], ah[mf][2], al[mf][2]);
        split_tf32(As[buf][r0+8][kc+tig+4], ah[mf][3], al[mf][3]);
      }
      uint32_t bh[NF][2], bl[NF][2];
      #pragma unroll
      for (int nf=0; nf<NF; nf++){
        int cc = wn + nf*8 + grp;
        split_tf32(Bs[buf][kc+tig  ][cc], bh[nf][0], bl[nf][0]);
        split_tf32(Bs[buf][kc+tig+4][cc], bh[nf][1], bl[nf][1]);
      }
      #pragma unroll
      for (int mf=0; mf<MF; mf++)
        #pragma unroll
        for (int nf=0; nf<NF; nf++){
          mma_tf32(acc[mf][nf], ah[mf], bh[nf]);
          mma_tf32(acc[mf][nf], al[mf], bh[nf]);
          mma_tf32(acc[mf][nf], ah[mf], bl[nf]);
        }
    }
    __syncthreads();
  }

  // ---- epilogue ----
  #pragma unroll
  for (int mf=0; mf<MF; mf++){
    #pragma unroll
    for (int nf=0; nf<NF; nf++){
      int row = m0 + wm + mf*16 + grp;
      int col = n0 + wn + nf*8 + tig*2;
      if (col < N){
        float2 v0 = make_float2(acc[mf][nf][0], acc[mf][nf][1]);
        float2 v1 = make_float2(acc[mf][nf][2], acc[mf][nf][3]);
        if (bias){
          float2 bv = *reinterpret_cast<const float2*>(bias + col);
          v0.x += bv.x; v0.y += bv.y;
          v1.x += bv.x; v1.y += bv.y;
        }
        if (ACT == 1){
          v0.x = gelu_exact(v0.x); v0.y = gelu_exact(v0.y);
          v1.x = gelu_exact(v1.x); v1.y = gelu_exact(v1.y);
        }
        *reinterpret_cast<float2*>(C + (size_t)row*ldc + col)     = v0;
        *reinterpret_cast<float2*>(C + (size_t)(row+8)*ldc + col) = v1;
      }
    }
  }
}

// ---------------- embeddings + LN --------------------------------------------
__global__ void embed_ln_kernel(const int* __restrict__ ids,
                                const float* __restrict__ we,
                                const float* __restrict__ pe,
                                const float* __restrict__ te,
                                const float* __restrict__ g,
                                const float* __restrict__ b)
{
  int t = blockIdx.x;
  int s = t & (SS-1);
  int id = ids[t];
  const float* wrow = we + (size_t)id*HH;
  const float* prow = pe + (size_t)s*HH;
  float x[3];
  float lsum = 0.f;
  #pragma unroll
  for (int i=0;i<3;i++){
    int c = threadIdx.x + i*256;
    x[i] = wrow[c] + prow[c] + te[c];
    lsum += x[i];
  }
  float mean = blockSum<8>(lsum) * (1.0f/HH);
  float ls2 = 0.f;
  #pragma unroll
  for (int i=0;i<3;i++){ x[i] -= mean; ls2 += x[i]*x[i]; }
  float var = blockSum<8>(ls2) * (1.0f/HH);
  float inv = rsqrtf(var + 1e-12f);
  #pragma unroll
  for (int i=0;i<3;i++){
    int c = threadIdx.x + i*256;
    g_h[(size_t)t*HH + c] = x[i]*inv*g[c] + b[c];
  }
}

// ---------------- residual + LN (in place on g_h) ----------------------------
__global__ void resln_kernel(const float* __restrict__ r,
                             const float* __restrict__ g,
                             const float* __restrict__ b)
{
  int t = blockIdx.x;
  float x[3];
  float lsum = 0.f;
  #pragma unroll
  for (int i=0;i<3;i++){
    int c = threadIdx.x + i*256;
    x[i] = g_h[(size_t)t*HH + c] + r[(size_t)t*HH + c];
    lsum += x[i];
  }
  float mean = blockSum<8>(lsum) * (1.0f/HH);
  float ls2 = 0.f;
  #pragma unroll
  for (int i=0;i<3;i++){ x[i] -= mean; ls2 += x[i]*x[i]; }
  float var = blockSum<8>(ls2) * (1.0f/HH);
  float inv = rsqrtf(var + 1e-12f);
  #pragma unroll
  for (int i=0;i<3;i++){
    int c = threadIdx.x + i*256;
    g_h[(size_t)t*HH + c] = x[i]*inv*g[c] + b[c];
  }
}

// ---------------- masked softmax over scores (in place) ----------------------
__global__ void softmax_kernel()
{
  int z = blockIdx.y;
  int s = blockIdx.x;
  float* row = g_scores + ((size_t)z*SS + s)*SS;
  float x[4];
  float mx = -3.4e38f;
  #pragma unroll
  for (int i=0;i<4;i++){
    int j = threadIdx.x + i*128;
    float v = row[j] * 0.125f;
    if (!(j < PLEN || j <= s)) v += -1e9f;
    x[i] = v;
    mx = fmaxf(mx, v);
  }
  mx = blockMax<4>(mx);
  float ls = 0.f;
  #pragma unroll
  for (int i=0;i<4;i++){ x[i] = __expf(x[i] - mx); ls += x[i]; }
  float sum = blockSum<4>(ls);
  float inv = 1.0f / sum;
  #pragma unroll
  for (int i=0;i<4;i++){
    int j = threadIdx.x + i*128;
    row[j] = x[i] * inv;
  }
}

// ---------------- cross entropy over valid rows ------------------------------
__global__ void zero_loss_kernel(){ g_loss_sum = 0.f; }

__global__ void ce_kernel(const int* __restrict__ labels)
{
  int r = blockIdx.x;
  int bb = r / NVALID_PER_B;
  int s  = PLEN + (r - bb*NVALID_PER_B);
  const float* row = g_logits + (size_t)r*VV;
  int lab = labels[bb*SS + s];

  float mx = -3.4e38f;
  for (int j = threadIdx.x; j < VV; j += 256) mx = fmaxf(mx, row[j]);
  mx = blockMax<8>(mx);
  float ls = 0.f;
  for (int j = threadIdx.x; j < VV; j += 256) ls += __expf(row[j] - mx);
  float sum = blockSum<8>(ls);
  if (threadIdx.x == 0){
    float nll = (logf(sum) + mx) - row[lab];
    atomicAdd(&g_loss_sum, nll);
  }
}

__global__ void finalize_kernel(float* out){
  out[0] = g_loss_sum * (1.0f/(float)NVALID);
}

// ---------------- host orchestration -----------------------------------------
template<int BN, bool TRANSB, int ACT>
static void launch_mm(const float* A, const float* B, const float* bias, float* C,
                      int M, int N, int K, int lda, int ldb, int ldc,
                      int batchInner,
                      long long sA1, long long sA2, long long sB1, long long sB2,
                      long long sC1, long long sC2, int gz)
{
  dim3 grid((N + BN - 1)/BN, M/128, gz);
  gemm_mma<BN,TRANSB,ACT><<<grid, 256>>>(
      A, B, bias, C, M, N, K, lda, ldb, ldc,
      batchInner, sA1, sA2, sB1, sB2, sC1, sC2);
}

extern "C" void kernel_launch(void* const* d_in, const int* in_sizes, int n_in,
                              void* d_out, int out_size)
{
  const int*   input_ids = (const int*)  d_in[0];
  const int*   labels    = (const int*)  d_in[1];
  const float* word_emb  = (const float*)d_in[2];
  const float* pos_emb   = (const float*)d_in[3];
  const float* type_emb  = (const float*)d_in[4];
  const float* eg        = (const float*)d_in[5];
  const float* eb        = (const float*)d_in[6];
  const float* Wq = (const float*)d_in[7];  const float* bq = (const float*)d_in[8];
  const float* Wk = (const float*)d_in[9];  const float* bk = (const float*)d_in[10];
  const float* Wv = (const float*)d_in[11]; const float* bv = (const float*)d_in[12];
  const float* Wo = (const float*)d_in[13]; const float* bo = (const float*)d_in[14];
  const float* ln1g = (const float*)d_in[15]; const float* ln1b = (const float*)d_in[16];
  const float* W1 = (const float*)d_in[17]; const float* bf1 = (const float*)d_in[18];
  const float* W2 = (const float*)d_in[19]; const float* bf2 = (const float*)d_in[20];
  const float* ln2g = (const float*)d_in[21]; const float* ln2b = (const float*)d_in[22];
  const float* Wc = (const float*)d_in[23]; const float* bc = (const float*)d_in[24];
  float* out = (float*)d_out;

  float *p_h, *p_q, *p_k, *p_v, *p_ctx, *p_tmp, *p_ffn, *p_sc, *p_lg;
  cudaGetSymbolAddress((void**)&p_h,   g_h);
  cudaGetSymbolAddress((void**)&p_q,   g_q);
  cudaGetSymbolAddress((void**)&p_k,   g_k);
  cudaGetSymbolAddress((void**)&p_v,   g_v);
  cudaGetSymbolAddress((void**)&p_ctx, g_ctx);
  cudaGetSymbolAddress((void**)&p_tmp, g_tmp);
  cudaGetSymbolAddress((void**)&p_ffn, g_ffn);
  cudaGetSymbolAddress((void**)&p_sc,  g_scores);
  cudaGetSymbolAddress((void**)&p_lg,  g_logits);

  zero_loss_kernel<<<1,1>>>();
  embed_ln_kernel<<<NTOK,256>>>(input_ids, word_emb, pos_emb, type_emb, eg, eb);

  const long long HDsq = (long long)HH*HH;
  const long long headStride = (long long)SS*HH;
  const long long scStrideH  = (long long)SS*SS;
  const long long scStrideB  = (long long)NHH*SS*SS;

  for (int l = 0; l < LL; l++) {
    const float* wq = Wq + (size_t)l*HDsq; const float* bql = bq + (size_t)l*HH;
    const float* wk = Wk + (size_t)l*HDsq; const float* bkl = bk + (size_t)l*HH;
    const float* wv = Wv + (size_t)l*HDsq; const float* bvl = bv + (size_t)l*HH;
    const float* wo = Wo + (size_t)l*HDsq; const float* bol = bo + (size_t)l*HH;
    const float* w1 = W1 + (size_t)l*HH*FFF; const float* b1l = bf1 + (size_t)l*FFF;
    const float* w2 = W2 + (size_t)l*FFF*HH; const float* b2l = bf2 + (size_t)l*HH;

    // QKV projections: [4096,768] @ [768,768] + b (NN)
    launch_mm<128,false,0>(p_h, wq, bql, p_q, NTOK, HH, HH, HH, HH, HH,
                           1, 0,0, 0,0, 0,0, 1);
    launch_mm<128,false,0>(p_h, wk, bkl, p_k, NTOK, HH, HH, HH, HH, HH,
                           1, 0,0, 0,0, 0,0, 1);
    launch_mm<128,false,0>(p_h, wv, bvl, p_v, NTOK, HH, HH, HH, HH, HH,
                           1, 0,0, 0,0, 0,0, 1);

    // scores = q @ k^T (NT), batched z = b*NH + h
    launch_mm<128,true,0>(p_q, p_k, nullptr, p_sc,
                          SS, SS, DHH, HH, HH, SS,
                          NHH,
                          headStride, (long long)DHH,
                          headStride, (long long)DHH,
                          scStrideB,  scStrideH, BB*NHH);

    softmax_kernel<<<dim3(SS, BB*NHH), 128>>>();

    // ctx = attn @ v (NN), M=512, N=64, K=512
    launch_mm<64,false,0>(p_sc, p_v, nullptr, p_ctx,
                          SS, DHH, SS, SS, HH, HH,
                          NHH,
                          scStrideB,  scStrideH,
                          headStride, (long long)DHH,
                          headStride, (long long)DHH, BB*NHH);

    // output proj + residual LN
    launch_mm<128,false,0>(p_ctx, wo, bol, p_tmp, NTOK, HH, HH, HH, HH, HH,
                           1, 0,0, 0,0, 0,0, 1);
    resln_kernel<<<NTOK,256>>>(p_tmp, ln1g + (size_t)l*HH, ln1b + (size_t)l*HH);

    // FFN
    launch_mm<128,false,1>(p_h, w1, b1l, p_ffn, NTOK, FFF, HH, HH, FFF, FFF,
                           1, 0,0, 0,0, 0,0, 1);   // fused GELU
    launch_mm<128,false,0>(p_ffn, w2, b2l, p_tmp, NTOK, HH, FFF, FFF, HH, HH,
                           1, 0,0, 0,0, 0,0, 1);
    resln_kernel<<<NTOK,256>>>(p_tmp, ln2g + (size_t)l*HH, ln2b + (size_t)l*HH);
  }

  // logits for valid tokens only (rows s in [128,512) per batch, contiguous)
  launch_mm<128,false,0>(p_h + (size_t)PLEN*HH, Wc, bc, p_lg,
                         NVALID_PER_B, VV, HH, HH, VV, VV,
                         1,
                         (long long)SS*HH, 0,
                         0, 0,
                         (long long)NVALID_PER_B*VV, 0, BB);

  ce_kernel<<<NVALID,256>>>(labels);
  finalize_kernel<<<1,1>>>(out);
}

// round 4
// speedup vs baseline: 2.6280x; 1.2460x over previous
#include <cuda_runtime.h>
#include <cstdint>
#include <math.h>

// Problem constants
#define BB 8
#define SS 512
#define HH 768
#define NHH 12
#define DHH 64
#define LL 12
#define VV 21128
#define FFF 3072
#define PLEN 128
#define NTOK (BB*SS)
#define NVALID_PER_B (SS-PLEN)
#define NVALID (BB*NVALID_PER_B)

// ---------------- scratch (device globals; no allocations allowed) ----------
__device__ float g_h[NTOK*HH];
__device__ float g_q[NTOK*HH];
__device__ float g_k[NTOK*HH];
__device__ float g_v[NTOK*HH];
__device__ float g_ctx[NTOK*HH];
__device__ float g_tmp[NTOK*HH];
__device__ float g_ffn[NTOK*FFF];
__device__ float g_scores[(size_t)BB*NHH*SS*SS];
__device__ float g_logits[(size_t)NVALID*VV];
__device__ float g_loss_sum;

// ---------------- helpers ----------------------------------------------------
__device__ __forceinline__ float warpSum(float v){
  #pragma unroll
  for (int o=16;o;o>>=1) v += __shfl_xor_sync(0xffffffffu, v, o);
  return v;
}
__device__ __forceinline__ float warpMax(float v){
  #pragma unroll
  for (int o=16;o;o>>=1) v = fmaxf(v, __shfl_xor_sync(0xffffffffu, v, o));
  return v;
}
template<int NW>
__device__ __forceinline__ float blockSum(float v){
  __shared__ float sh[NW];
  __syncthreads();
  v = warpSum(v);
  if ((threadIdx.x & 31)==0) sh[threadIdx.x>>5] = v;
  __syncthreads();
  float r = 0.f;
  #pragma unroll
  for (int i=0;i<NW;i++) r += sh[i];
  return r;
}
template<int NW>
__device__ __forceinline__ float blockMax(float v){
  __shared__ float sh[NW];
  __syncthreads();
  v = warpMax(v);
  if ((threadIdx.x & 31)==0) sh[threadIdx.x>>5] = v;
  __syncthreads();
  float r = -3.4e38f;
  #pragma unroll
  for (int i=0;i<NW;i++) r = fmaxf(r, sh[i]);
  return r;
}
__device__ __forceinline__ float gelu_exact(float x){
  return 0.5f * x * (1.0f + erff(x * 0.70710678118654752f));
}

__device__ __forceinline__ uint32_t smem_u32(const void* p){
  uint32_t a;
  asm("{ .reg .u64 t; cvta.to.shared.u64 t, %1; cvt.u32.u64 %0, t; }" : "=r"(a) : "l"(p));
  return a;
}
__device__ __forceinline__ void cp16(uint32_t dst, const void* src){
  asm volatile("cp.async.ca.shared.global [%0], [%1], 16;" :: "r"(dst), "l"(src));
}
__device__ __forceinline__ void cp16p(uint32_t dst, const void* src, bool valid){
  int sz = valid ? 16 : 0;
  asm volatile("cp.async.ca.shared.global [%0], [%1], 16, %2;"
               :: "r"(dst), "l"(src), "r"(sz));
}
__device__ __forceinline__ void cp_commit(){
  asm volatile("cp.async.commit_group;" ::: "memory");
}
template<int N>
__device__ __forceinline__ void cp_wait(){
  asm volatile("cp.async.wait_group %0;" :: "n"(N) : "memory");
}

// split a pair of fp32 into packed bf16 hi and packed bf16 lo (x0 -> low half)
__device__ __forceinline__ void split_bf16_pair(float x0, float x1,
                                                uint32_t& hi, uint32_t& lo){
  uint32_t h;
  asm("cvt.rn.bf16x2.f32 %0, %1, %2;" : "=r"(h) : "f"(x1), "f"(x0));
  float h0 = __uint_as_float(h << 16);
  float h1 = __uint_as_float(h & 0xffff0000u);
  float l0 = x0 - h0;
  float l1 = x1 - h1;
  asm("cvt.rn.bf16x2.f32 %0, %1, %2;" : "=r"(lo) : "f"(l1), "f"(l0));
  hi = h;
}

__device__ __forceinline__ void mma_bf16(float* d, const uint32_t* a, const uint32_t* b){
  asm volatile(
    "mma.sync.aligned.m16n8k16.row.col.f32.bf16.bf16.f32 "
    "{%0,%1,%2,%3}, {%4,%5,%6,%7}, {%8,%9}, {%0,%1,%2,%3};\n"
    : "+f"(d[0]), "+f"(d[1]), "+f"(d[2]), "+f"(d[3])
    : "r"(a[0]), "r"(a[1]), "r"(a[2]), "r"(a[3]), "r"(b[0]), "r"(b[1]));
}

// ---------------- 3xBF16 mma.sync GEMM ---------------------------------------
// C[M,N] = A[M,K] @ op(B) (+bias)(+GELU). TRANSB: B is [N,K] (NT, C=A@B^T);
// else B is [K,N] (NN). BM=128 fixed, BK=16, cp.async double buffered.
// Each fp32 operand split into bf16 hi+lo at fragment load; 3 MMA terms
// (hh + lh + hl) give ~2^-17 per-product error, fp32 accumulate.
#define BKc 16

template<int BN, bool TRANSB, int ACT>
__global__ __launch_bounds__(256) void gemm_mma(
    const float* __restrict__ Ag, const float* __restrict__ Bg,
    const float* __restrict__ bias, float* __restrict__ Cg,
    int M, int N, int K, int lda, int ldb, int ldc,
    int batchInner,
    long long sA1, long long sA2, long long sB1, long long sB2,
    long long sC1, long long sC2)
{
  constexpr int BM = 128;
  constexpr int WARPS_M = (BN==128) ? 2 : 4;
  constexpr int WARPS_N = 8 / WARPS_M;
  constexpr int WM = BM / WARPS_M;       // 64 or 32
  constexpr int WN = BN / WARPS_N;       // 32
  constexpr int MF = WM / 16;            // 4 or 2
  constexpr int NF = WN / 8;             // 4

  __shared__ float As[2][BM][BKc+4];     // raw fp32, row-major [m][k]
  __shared__ float Bs[2][BKc][BN+8];     // raw fp32, [k][n]

  const int tid  = threadIdx.x;
  const int wid  = tid >> 5;
  const int lane = tid & 31;
  const int grp  = lane >> 2;            // 0..7
  const int tig  = lane & 3;             // 0..3

  const int z  = blockIdx.z;
  const int zo = z / batchInner;
  const int zi = z - zo * batchInner;
  const float* A  = Ag + zo*sA1 + zi*sA2;
  const float* Bp = Bg + zo*sB1 + zi*sB2;
  float*       C  = Cg + zo*sC1 + zi*sC2;

  const int m0 = blockIdx.y * BM;
  const int n0 = blockIdx.x * BN;
  const int wm = (wid / WARPS_N) * WM;
  const int wn = (wid % WARPS_N) * WN;

  float acc[MF][NF][4];
  #pragma unroll
  for (int i=0;i<MF;i++)
    #pragma unroll
    for (int j=0;j<NF;j++)
      #pragma unroll
      for (int r=0;r<4;r++) acc[i][j][r] = 0.f;

  const int nch = K / BKc;

  // ---- tile loaders ----
  auto loadA = [&](int c, int buf){
    int k0 = c * BKc;
    #pragma unroll
    for (int i=0;i<2;i++){
      int idx = i*256 + tid;
      int row = idx >> 2;                // 0..127
      int kg  = idx & 3;                 // 0..3 (float4 within 16)
      uint32_t dst = smem_u32(&As[buf][row][kg*4]);
      cp16(dst, A + (size_t)(m0+row)*lda + k0 + kg*4);
    }
  };
  auto loadB = [&](int c, int buf){
    int k0 = c * BKc;
    if (TRANSB){
      // B[N,K]; write Bs[k][n] transposed (direct stores; N assumed full tile)
      int n  = tid & 127;
      int hf = tid >> 7;                 // 0/1 -> k-halves of 8
      const float* src = Bp + (size_t)(n0+n)*ldb + k0 + hf*8;
      float4 v0 = *reinterpret_cast<const float4*>(src);
      float4 v1 = *reinterpret_cast<const float4*>(src+4);
      Bs[buf][hf*8+0][n] = v0.x; Bs[buf][hf*8+1][n] = v0.y;
      Bs[buf][hf*8+2][n] = v0.z; Bs[buf][hf*8+3][n] = v0.w;
      Bs[buf][hf*8+4][n] = v1.x; Bs[buf][hf*8+5][n] = v1.y;
      Bs[buf][hf*8+6][n] = v1.z; Bs[buf][hf*8+7][n] = v1.w;
    } else {
      constexpr int NB4 = BKc*BN/4/256;  // float4 per thread (2 or 1)
      #pragma unroll
      for (int i=0;i<NB4;i++){
        int idx = i*256 + tid;
        int k  = idx / (BN/4);
        int ng = idx % (BN/4);
        int gn = n0 + ng*4;
        uint32_t dst = smem_u32(&Bs[buf][k][ng*4]);
        bool valid = (gn < N);
        const float* src = valid ? (Bp + (size_t)(k0+k)*ldb + gn) : Bp;
        cp16p(dst, src, valid);
      }
    }
  };

  // ---- prologue ----
  loadA(0, 0);
  loadB(0, 0);
  cp_commit();

  for (int c = 0; c < nch; c++){
    const int buf = c & 1;
    if (c+1 < nch){
      loadA(c+1, buf^1);
      loadB(c+1, buf^1);
      cp_commit();
      cp_wait<1>();
    } else {
      cp_wait<0>();
    }
    __syncthreads();

    // ---- compute one m16n8k16 step on buf ----
    uint32_t ah[MF][4], al[MF][4];
    #pragma unroll
    for (int mf=0; mf<MF; mf++){
      int r0 = wm + mf*16 + grp;
      float2 p0 = *reinterpret_cast<const float2*>(&As[buf][r0  ][2*tig  ]);
      float2 p1 = *reinterpret_cast<const float2*>(&As[buf][r0+8][2*tig  ]);
      float2 p2 = *reinterpret_cast<const float2*>(&As[buf][r0  ][2*tig+8]);
      float2 p3 = *reinterpret_cast<const float2*>(&As[buf][r0+8][2*tig+8]);
      split_bf16_pair(p0.x, p0.y, ah[mf][0], al[mf][0]);
      split_bf16_pair(p1.x, p1.y, ah[mf][1], al[mf][1]);
      split_bf16_pair(p2.x, p2.y, ah[mf][2], al[mf][2]);
      split_bf16_pair(p3.x, p3.y, ah[mf][3], al[mf][3]);
    }
    uint32_t bh[NF][2], bl[NF][2];
    #pragma unroll
    for (int nf=0; nf<NF; nf++){
      int cc = wn + nf*8 + grp;
      float x0 = Bs[buf][2*tig  ][cc];
      float x1 = Bs[buf][2*tig+1][cc];
      float x2 = Bs[buf][2*tig+8][cc];
      float x3 = Bs[buf][2*tig+9][cc];
      split_bf16_pair(x0, x1, bh[nf][0], bl[nf][0]);
      split_bf16_pair(x2, x3, bh[nf][1], bl[nf][1]);
    }
    #pragma unroll
    for (int mf=0; mf<MF; mf++)
      #pragma unroll
      for (int nf=0; nf<NF; nf++){
        mma_bf16(acc[mf][nf], ah[mf], bh[nf]);
        mma_bf16(acc[mf][nf], al[mf], bh[nf]);
        mma_bf16(acc[mf][nf], ah[mf], bl[nf]);
      }
    __syncthreads();
  }

  // ---- epilogue ----
  #pragma unroll
  for (int mf=0; mf<MF; mf++){
    #pragma unroll
    for (int nf=0; nf<NF; nf++){
      int row = m0 + wm + mf*16 + grp;
      int col = n0 + wn + nf*8 + tig*2;
      if (col < N){
        float2 v0 = make_float2(acc[mf][nf][0], acc[mf][nf][1]);
        float2 v1 = make_float2(acc[mf][nf][2], acc[mf][nf][3]);
        if (bias){
          float2 bv = *reinterpret_cast<const float2*>(bias + col);
          v0.x += bv.x; v0.y += bv.y;
          v1.x += bv.x; v1.y += bv.y;
        }
        if (ACT == 1){
          v0.x = gelu_exact(v0.x); v0.y = gelu_exact(v0.y);
          v1.x = gelu_exact(v1.x); v1.y = gelu_exact(v1.y);
        }
        *reinterpret_cast<float2*>(C + (size_t)row*ldc + col)     = v0;
        *reinterpret_cast<float2*>(C + (size_t)(row+8)*ldc + col) = v1;
      }
    }
  }
}

// ---------------- embeddings + LN --------------------------------------------
__global__ void embed_ln_kernel(const int* __restrict__ ids,
                                const float* __restrict__ we,
                                const float* __restrict__ pe,
                                const float* __restrict__ te,
                                const float* __restrict__ g,
                                const float* __restrict__ b)
{
  int t = blockIdx.x;
  int s = t & (SS-1);
  int id = ids[t];
  const float* wrow = we + (size_t)id*HH;
  const float* prow = pe + (size_t)s*HH;
  float x[3];
  float lsum = 0.f;
  #pragma unroll
  for (int i=0;i<3;i++){
    int c = threadIdx.x + i*256;
    x[i] = wrow[c] + prow[c] + te[c];
    lsum += x[i];
  }
  float mean = blockSum<8>(lsum) * (1.0f/HH);
  float ls2 = 0.f;
  #pragma unroll
  for (int i=0;i<3;i++){ x[i] -= mean; ls2 += x[i]*x[i]; }
  float var = blockSum<8>(ls2) * (1.0f/HH);
  float inv = rsqrtf(var + 1e-12f);
  #pragma unroll
  for (int i=0;i<3;i++){
    int c = threadIdx.x + i*256;
    g_h[(size_t)t*HH + c] = x[i]*inv*g[c] + b[c];
  }
}

// ---------------- residual + LN (in place on g_h) ----------------------------
__global__ void resln_kernel(const float* __restrict__ r,
                             const float* __restrict__ g,
                             const float* __restrict__ b)
{
  int t = blockIdx.x;
  float x[3];
  float lsum = 0.f;
  #pragma unroll
  for (int i=0;i<3;i++){
    int c = threadIdx.x + i*256;
    x[i] = g_h[(size_t)t*HH + c] + r[(size_t)t*HH + c];
    lsum += x[i];
  }
  float mean = blockSum<8>(lsum) * (1.0f/HH);
  float ls2 = 0.f;
  #pragma unroll
  for (int i=0;i<3;i++){ x[i] -= mean; ls2 += x[i]*x[i]; }
  float var = blockSum<8>(ls2) * (1.0f/HH);
  float inv = rsqrtf(var + 1e-12f);
  #pragma unroll
  for (int i=0;i<3;i++){
    int c = threadIdx.x + i*256;
    g_h[(size_t)t*HH + c] = x[i]*inv*g[c] + b[c];
  }
}

// ---------------- masked softmax over scores (in place) ----------------------
__global__ void softmax_kernel()
{
  int z = blockIdx.y;
  int s = blockIdx.x;
  float* row = g_scores + ((size_t)z*SS + s)*SS;
  float x[4];
  float mx = -3.4e38f;
  #pragma unroll
  for (int i=0;i<4;i++){
    int j = threadIdx.x + i*128;
    float v = row[j] * 0.125f;
    if (!(j < PLEN || j <= s)) v += -1e9f;
    x[i] = v;
    mx = fmaxf(mx, v);
  }
  mx = blockMax<4>(mx);
  float ls = 0.f;
  #pragma unroll
  for (int i=0;i<4;i++){ x[i] = __expf(x[i] - mx); ls += x[i]; }
  float sum = blockSum<4>(ls);
  float inv = 1.0f / sum;
  #pragma unroll
  for (int i=0;i<4;i++){
    int j = threadIdx.x + i*128;
    row[j] = x[i] * inv;
  }
}

// ---------------- cross entropy over valid rows ------------------------------
__global__ void zero_loss_kernel(){ g_loss_sum = 0.f; }

__global__ void ce_kernel(const int* __restrict__ labels)
{
  int r = blockIdx.x;
  int bb = r / NVALID_PER_B;
  int s  = PLEN + (r - bb*NVALID_PER_B);
  const float* row = g_logits + (size_t)r*VV;
  int lab = labels[bb*SS + s];

  float mx = -3.4e38f;
  for (int j = threadIdx.x; j < VV; j += 256) mx = fmaxf(mx, row[j]);
  mx = blockMax<8>(mx);
  float ls = 0.f;
  for (int j = threadIdx.x; j < VV; j += 256) ls += __expf(row[j] - mx);
  float sum = blockSum<8>(ls);
  if (threadIdx.x == 0){
    float nll = (logf(sum) + mx) - row[lab];
    atomicAdd(&g_loss_sum, nll);
  }
}

__global__ void finalize_kernel(float* out){
  out[0] = g_loss_sum * (1.0f/(float)NVALID);
}

// ---------------- host orchestration -----------------------------------------
template<int BN, bool TRANSB, int ACT>
static void launch_mm(const float* A, const float* B, const float* bias, float* C,
                      int M, int N, int K, int lda, int ldb, int ldc,
                      int batchInner,
                      long long sA1, long long sA2, long long sB1, long long sB2,
                      long long sC1, long long sC2, int gz)
{
  dim3 grid((N + BN - 1)/BN, M/128, gz);
  gemm_mma<BN,TRANSB,ACT><<<grid, 256>>>(
      A, B, bias, C, M, N, K, lda, ldb, ldc,
      batchInner, sA1, sA2, sB1, sB2, sC1, sC2);
}

extern "C" void kernel_launch(void* const* d_in, const int* in_sizes, int n_in,
                              void* d_out, int out_size)
{
  const int*   input_ids = (const int*)  d_in[0];
  const int*   labels    = (const int*)  d_in[1];
  const float* word_emb  = (const float*)d_in[2];
  const float* pos_emb   = (const float*)d_in[3];
  const float* type_emb  = (const float*)d_in[4];
  const float* eg        = (const float*)d_in[5];
  const float* eb        = (const float*)d_in[6];
  const float* Wq = (const float*)d_in[7];  const float* bq = (const float*)d_in[8];
  const float* Wk = (const float*)d_in[9];  const float* bk = (const float*)d_in[10];
  const float* Wv = (const float*)d_in[11]; const float* bv = (const float*)d_in[12];
  const float* Wo = (const float*)d_in[13]; const float* bo = (const float*)d_in[14];
  const float* ln1g = (const float*)d_in[15]; const float* ln1b = (const float*)d_in[16];
  const float* W1 = (const float*)d_in[17]; const float* bf1 = (const float*)d_in[18];
  const float* W2 = (const float*)d_in[19]; const float* bf2 = (const float*)d_in[20];
  const float* ln2g = (const float*)d_in[21]; const float* ln2b = (const float*)d_in[22];
  const float* Wc = (const float*)d_in[23]; const float* bc = (const float*)d_in[24];
  float* out = (float*)d_out;

  float *p_h, *p_q, *p_k, *p_v, *p_ctx, *p_tmp, *p_ffn, *p_sc, *p_lg;
  cudaGetSymbolAddress((void**)&p_h,   g_h);
  cudaGetSymbolAddress((void**)&p_q,   g_q);
  cudaGetSymbolAddress((void**)&p_k,   g_k);
  cudaGetSymbolAddress((void**)&p_v,   g_v);
  cudaGetSymbolAddress((void**)&p_ctx, g_ctx);
  cudaGetSymbolAddress((void**)&p_tmp, g_tmp);
  cudaGetSymbolAddress((void**)&p_ffn, g_ffn);
  cudaGetSymbolAddress((void**)&p_sc,  g_scores);
  cudaGetSymbolAddress((void**)&p_lg,  g_logits);

  zero_loss_kernel<<<1,1>>>();
  embed_ln_kernel<<<NTOK,256>>>(input_ids, word_emb, pos_emb, type_emb, eg, eb);

  const long long HDsq = (long long)HH*HH;
  const long long headStride = (long long)SS*HH;
  const long long scStrideH  = (long long)SS*SS;
  const long long scStrideB  = (long long)NHH*SS*SS;

  for (int l = 0; l < LL; l++) {
    const float* wq = Wq + (size_t)l*HDsq; const float* bql = bq + (size_t)l*HH;
    const float* wk = Wk + (size_t)l*HDsq; const float* bkl = bk + (size_t)l*HH;
    const float* wv = Wv + (size_t)l*HDsq; const float* bvl = bv + (size_t)l*HH;
    const float* wo = Wo + (size_t)l*HDsq; const float* bol = bo + (size_t)l*HH;
    const float* w1 = W1 + (size_t)l*HH*FFF; const float* b1l = bf1 + (size_t)l*FFF;
    const float* w2 = W2 + (size_t)l*FFF*HH; const float* b2l = bf2 + (size_t)l*HH;

    // QKV projections: [4096,768] @ [768,768] + b (NN)
    launch_mm<128,false,0>(p_h, wq, bql, p_q, NTOK, HH, HH, HH, HH, HH,
                           1, 0,0, 0,0, 0,0, 1);
    launch_mm<128,false,0>(p_h, wk, bkl, p_k, NTOK, HH, HH, HH, HH, HH,
                           1, 0,0, 0,0, 0,0, 1);
    launch_mm<128,false,0>(p_h, wv, bvl, p_v, NTOK, HH, HH, HH, HH, HH,
                           1, 0,0, 0,0, 0,0, 1);

    // scores = q @ k^T (NT), batched z = b*NH + h
    launch_mm<128,true,0>(p_q, p_k, nullptr, p_sc,
                          SS, SS, DHH, HH, HH, SS,
                          NHH,
                          headStride, (long long)DHH,
                          headStride, (long long)DHH,
                          scStrideB,  scStrideH, BB*NHH);

    softmax_kernel<<<dim3(SS, BB*NHH), 128>>>();

    // ctx = attn @ v (NN), M=512, N=64, K=512
    launch_mm<64,false,0>(p_sc, p_v, nullptr, p_ctx,
                          SS, DHH, SS, SS, HH, HH,
                          NHH,
                          scStrideB,  scStrideH,
                          headStride, (long long)DHH,
                          headStride, (long long)DHH, BB*NHH);

    // output proj + residual LN
    launch_mm<128,false,0>(p_ctx, wo, bol, p_tmp, NTOK, HH, HH, HH, HH, HH,
                           1, 0,0, 0,0, 0,0, 1);
    resln_kernel<<<NTOK,256>>>(p_tmp, ln1g + (size_t)l*HH, ln1b + (size_t)l*HH);

    // FFN
    launch_mm<128,false,1>(p_h, w1, b1l, p_ffn, NTOK, FFF, HH, HH, FFF, FFF,
                           1, 0,0, 0,0, 0,0, 1);   // fused GELU
    launch_mm<128,false,0>(p_ffn, w2, b2l, p_tmp, NTOK, HH, FFF, FFF, HH, HH,
                           1, 0,0, 0,0, 0,0, 1);
    resln_kernel<<<NTOK,256>>>(p_tmp, ln2g + (size_t)l*HH, ln2b + (size_t)l*HH);
  }

  // logits for valid tokens only (rows s in [128,512) per batch, contiguous)
  launch_mm<128,false,0>(p_h + (size_t)PLEN*HH, Wc, bc, p_lg,
                         NVALID_PER_B, VV, HH, HH, VV, VV,
                         1,
                         (long long)SS*HH, 0,
                         0, 0,
                         (long long)NVALID_PER_B*VV, 0, BB);

  ce_kernel<<<NVALID,256>>>(labels);
  finalize_kernel<<<1,1>>>(out);
}

// round 7
// speedup vs baseline: 2.7841x; 1.0594x over previous
#include <cuda_runtime.h>
#include <cuda_bf16.h>
#include <cstdint>
#include <math.h>

// Problem constants
#define BB 8
#define SS 512
#define HH 768
#define NHH 12
#define DHH 64
#define LL 12
#define VV 21128
#define FFF 3072
#define PLEN 128
#define NTOK (BB*SS)
#define NVALID_PER_B (SS-PLEN)
#define NVALID (BB*NVALID_PER_B)

// ---------------- scratch (device globals; no allocations allowed) ----------
__device__ float g_h[NTOK*HH];
__device__ float g_q[NTOK*HH];
__device__ float g_k[NTOK*HH];
__device__ float g_v[NTOK*HH];
__device__ float g_ctx[NTOK*HH];
__device__ float g_tmp[NTOK*HH];
__device__ float g_ffn[NTOK*FFF];
__device__ float g_scores[(size_t)BB*NHH*SS*SS];
__device__ float g_logits[(size_t)NVALID*VV];
__device__ float g_loss_sum;

// ---------------- helpers ----------------------------------------------------
__device__ __forceinline__ float warpSum(float v){
  #pragma unroll
  for (int o=16;o;o>>=1) v += __shfl_xor_sync(0xffffffffu, v, o);
  return v;
}
__device__ __forceinline__ float warpMax(float v){
  #pragma unroll
  for (int o=16;o;o>>=1) v = fmaxf(v, __shfl_xor_sync(0xffffffffu, v, o));
  return v;
}
template<int NW>
__device__ __forceinline__ float blockSum(float v){
  __shared__ float sh[NW];
  __syncthreads();
  v = warpSum(v);
  if ((threadIdx.x & 31)==0) sh[threadIdx.x>>5] = v;
  __syncthreads();
  float r = 0.f;
  #pragma unroll
  for (int i=0;i<NW;i++) r += sh[i];
  return r;
}
template<int NW>
__device__ __forceinline__ float blockMax(float v){
  __shared__ float sh[NW];
  __syncthreads();
  v = warpMax(v);
  if ((threadIdx.x & 31)==0) sh[threadIdx.x>>5] = v;
  __syncthreads();
  float r = -3.4e38f;
  #pragma unroll
  for (int i=0;i<NW;i++) r = fmaxf(r, sh[i]);
  return r;
}
__device__ __forceinline__ float gelu_exact(float x){
  return 0.5f * x * (1.0f + erff(x * 0.70710678118654752f));
}

__device__ __forceinline__ uint32_t smem_u32(const void* p){
  uint32_t a;
  asm("{ .reg .u64 t; cvta.to.shared.u64 t, %1; cvt.u32.u64 %0, t; }" : "=r"(a) : "l"(p));
  return a;
}

// split a pair of fp32 into packed bf16 hi and packed bf16 lo (x0 -> low half)
__device__ __forceinline__ void split_bf16_pair(float x0, float x1,
                                                uint32_t& hi, uint32_t& lo){
  uint32_t h;
  asm("cvt.rn.bf16x2.f32 %0, %1, %2;" : "=r"(h) : "f"(x1), "f"(x0));
  float h0 = __uint_as_float(h << 16);
  float h1 = __uint_as_float(h & 0xffff0000u);
  float l0 = x0 - h0;
  float l1 = x1 - h1;
  asm("cvt.rn.bf16x2.f32 %0, %1, %2;" : "=r"(lo) : "f"(l1), "f"(l0));
  hi = h;
}

__device__ __forceinline__ void mma_bf16(float* d, const uint32_t* a, const uint32_t* b){
  asm volatile(
    "mma.sync.aligned.m16n8k16.row.col.f32.bf16.bf16.f32 "
    "{%0,%1,%2,%3}, {%4,%5,%6,%7}, {%8,%9}, {%0,%1,%2,%3};\n"
    : "+f"(d[0]), "+f"(d[1]), "+f"(d[2]), "+f"(d[3])
    : "r"(a[0]), "r"(a[1]), "r"(a[2]), "r"(a[3]), "r"(b[0]), "r"(b[1]));
}
__device__ __forceinline__ void ldsm_x4(uint32_t* r, uint32_t addr){
  asm volatile("ldmatrix.sync.aligned.m8n8.x4.shared.b16 {%0,%1,%2,%3}, [%4];"
    : "=r"(r[0]), "=r"(r[1]), "=r"(r[2]), "=r"(r[3]) : "r"(addr));
}
__device__ __forceinline__ void ldsm_x4_t(uint32_t* r, uint32_t addr){
  asm volatile("ldmatrix.sync.aligned.m8n8.x4.trans.shared.b16 {%0,%1,%2,%3}, [%4];"
    : "=r"(r[0]), "=r"(r[1]), "=r"(r[2]), "=r"(r[3]) : "r"(addr));
}

// ---------------- 3xBF16 mma.sync GEMM with pre-split smem + ldmatrix --------
// C[M,N] = A[M,K] @ op(B) (+bias)(+GELU). TRANSB: B is [N,K] (NT, C=A@B^T);
// else B is [K,N] (NN). BM=128, BK=16, register-prefetch double buffering.
// Loaders split fp32 -> bf16 hi/lo ONCE; fragments via ldmatrix.
// NOTE: ldmatrix row starts must be 16B-aligned -> all strides multiple of 8 bf16.

template<int BN, bool TRANSB, int ACT>
__global__ __launch_bounds__(256,1) void gemm_mma(
    const float* __restrict__ Ag, const float* __restrict__ Bg,
    const float* __restrict__ bias, float* __restrict__ Cg,
    int M, int N, int K, int lda, int ldb, int ldc,
    int batchInner,
    long long sA1, long long sA2, long long sB1, long long sB2,
    long long sC1, long long sC2)
{
  constexpr int BM = 128;
  constexpr int BK = 16;
  constexpr int WARPS_M = (BN==128) ? 2 : 4;
  constexpr int WARPS_N = 8 / WARPS_M;
  constexpr int WM = BM / WARPS_M;       // 64 or 32
  constexpr int WN = BN / WARPS_N;       // 32
  constexpr int MF = WM / 16;            // 4 or 2
  constexpr int NF = WN / 8;             // 4

  constexpr int AP = 24;                               // A row stride (bf16, 48B: 16B-aligned rows, conflict-free)
  constexpr int BROWS = TRANSB ? BN : BK;
  constexpr int BP = TRANSB ? 24 : (BN + 8);           // B row stride (bf16; both multiples of 8)

  __shared__ __align__(16) __nv_bfloat16 Ah[2][BM][AP];
  __shared__ __align__(16) __nv_bfloat16 Al[2][BM][AP];
  __shared__ __align__(16) __nv_bfloat16 Bh[2][BROWS][BP];
  __shared__ __align__(16) __nv_bfloat16 Bl[2][BROWS][BP];

  const int tid  = threadIdx.x;
  const int wid  = tid >> 5;
  const int lane = tid & 31;
  const int grp  = lane >> 2;
  const int tig  = lane & 3;

  const int z  = blockIdx.z;
  const int zo = z / batchInner;
  const int zi = z - zo * batchInner;
  const float* A  = Ag + zo*sA1 + zi*sA2;
  const float* Bp = Bg + zo*sB1 + zi*sB2;
  float*       C  = Cg + zo*sC1 + zi*sC2;

  const int m0 = blockIdx.y * BM;
  const int n0 = blockIdx.x * BN;
  const int wm = (wid / WARPS_N) * WM;
  const int wn = (wid % WARPS_N) * WN;

  float acc[MF][NF][4];
  #pragma unroll
  for (int i=0;i<MF;i++)
    #pragma unroll
    for (int j=0;j<NF;j++)
      #pragma unroll
      for (int r=0;r<4;r++) acc[i][j][r] = 0.f;

  const int nch = K / BK;

  // register staging for global tiles
  float4 aReg[2];
  constexpr int NB4 = TRANSB ? 2 : (BK*BN/4/256);      // float4 per thread
  float4 bReg[NB4];

  // loader index precompute
  const int aRow0 = tid >> 2;            // 0..63 (i=0), +64 (i=1)
  const int aKg   = tid & 3;

  auto ldgA = [&](int c){
    int k0 = c * BK;
    #pragma unroll
    for (int i=0;i<2;i++){
      int row = aRow0 + i*64;
      aReg[i] = *reinterpret_cast<const float4*>(A + (size_t)(m0+row)*lda + k0 + aKg*4);
    }
  };
  auto stsA = [&](int buf){
    #pragma unroll
    for (int i=0;i<2;i++){
      int row = aRow0 + i*64;
      uint32_t h0,l0,h1,l1;
      split_bf16_pair(aReg[i].x, aReg[i].y, h0, l0);
      split_bf16_pair(aReg[i].z, aReg[i].w, h1, l1);
      *reinterpret_cast<uint2*>(&Ah[buf][row][aKg*4]) = make_uint2(h0,h1);
      *reinterpret_cast<uint2*>(&Al[buf][row][aKg*4]) = make_uint2(l0,l1);
    }
  };

  auto ldgB = [&](int c){
    int k0 = c * BK;
    if (TRANSB){
      int n  = tid & 127;
      int hf = tid >> 7;
      const float* src = Bp + (size_t)(n0+n)*ldb + k0 + hf*8;
      bReg[0] = *reinterpret_cast<const float4*>(src);
      if (NB4 > 1) bReg[NB4-1] = *reinterpret_cast<const float4*>(src+4);
    } else {
      #pragma unroll
      for (int i=0;i<NB4;i++){
        int idx = i*256 + tid;
        int k  = idx / (BN/4);
        int ng = idx % (BN/4);
        int gn = n0 + ng*4;
        if (gn < N)
          bReg[i] = *reinterpret_cast<const float4*>(Bp + (size_t)(k0+k)*ldb + gn);
        else
          bReg[i] = make_float4(0.f,0.f,0.f,0.f);
      }
    }
  };
  auto stsB = [&](int buf){
    if (TRANSB){
      int n  = tid & 127;
      int hf = tid >> 7;
      uint32_t h0,l0,h1,l1,h2,l2,h3,l3;
      split_bf16_pair(bReg[0].x, bReg[0].y, h0, l0);
      split_bf16_pair(bReg[0].z, bReg[0].w, h1, l1);
      split_bf16_pair(bReg[NB4-1].x, bReg[NB4-1].y, h2, l2);
      split_bf16_pair(bReg[NB4-1].z, bReg[NB4-1].w, h3, l3);
      *reinterpret_cast<uint2*>(&Bh[buf][n][hf*8])   = make_uint2(h0,h1);
      *reinterpret_cast<uint2*>(&Bh[buf][n][hf*8+4]) = make_uint2(h2,h3);
      *reinterpret_cast<uint2*>(&Bl[buf][n][hf*8])   = make_uint2(l0,l1);
      *reinterpret_cast<uint2*>(&Bl[buf][n][hf*8+4]) = make_uint2(l2,l3);
    } else {
      #pragma unroll
      for (int i=0;i<NB4;i++){
        int idx = i*256 + tid;
        int k  = idx / (BN/4);
        int ng = idx % (BN/4);
        uint32_t h0,l0,h1,l1;
        split_bf16_pair(bReg[i].x, bReg[i].y, h0, l0);
        split_bf16_pair(bReg[i].z, bReg[i].w, h1, l1);
        *reinterpret_cast<uint2*>(&Bh[buf][k][ng*4]) = make_uint2(h0,h1);
        *reinterpret_cast<uint2*>(&Bl[buf][k][ng*4]) = make_uint2(l0,l1);
      }
    }
  };

  // ldmatrix lane decodes
  const int lrow = lane & 7;
  const int lsel = (lane >> 3) & 1;
  const int lhi  = lane >> 4;

  // ---- prologue ----
  ldgA(0); ldgB(0);
  stsA(0); stsB(0);
  __syncthreads();

  for (int c = 0; c < nch; c++){
    const int buf = c & 1;
    if (c+1 < nch){ ldgA(c+1); ldgB(c+1); }

    // ---- fragment loads via ldmatrix ----
    uint32_t ah[MF][4], al[MF][4];
    #pragma unroll
    for (int mf=0; mf<MF; mf++){
      int r = wm + mf*16 + lsel*8 + lrow;
      ldsm_x4(ah[mf], smem_u32(&Ah[buf][r][lhi*8]));
      ldsm_x4(al[mf], smem_u32(&Al[buf][r][lhi*8]));
    }
    uint32_t bh[NF][2], bl[NF][2];
    #pragma unroll
    for (int nfp=0; nfp<NF/2; nfp++){
      int nb = wn + nfp*16;
      uint32_t rh[4], rl[4];
      if (TRANSB){
        int r = nb + lhi*8 + lrow;
        ldsm_x4(rh, smem_u32(&Bh[buf][r][lsel*8]));
        ldsm_x4(rl, smem_u32(&Bl[buf][r][lsel*8]));
      } else {
        int r = lsel*8 + lrow;
        ldsm_x4_t(rh, smem_u32(&Bh[buf][r][nb + lhi*8]));
        ldsm_x4_t(rl, smem_u32(&Bl[buf][r][nb + lhi*8]));
      }
      bh[2*nfp][0]=rh[0]; bh[2*nfp][1]=rh[1]; bh[2*nfp+1][0]=rh[2]; bh[2*nfp+1][1]=rh[3];
      bl[2*nfp][0]=rl[0]; bl[2*nfp][1]=rl[1]; bl[2*nfp+1][0]=rl[2]; bl[2*nfp+1][1]=rl[3];
    }

    #pragma unroll
    for (int mf=0; mf<MF; mf++)
      #pragma unroll
      for (int nf=0; nf<NF; nf++){
        mma_bf16(acc[mf][nf], ah[mf], bh[nf]);
        mma_bf16(acc[mf][nf], al[mf], bh[nf]);
        mma_bf16(acc[mf][nf], ah[mf], bl[nf]);
      }

    __syncthreads();
    if (c+1 < nch){
      stsA(buf^1); stsB(buf^1);
      __syncthreads();
    }
  }

  // ---- epilogue ----
  #pragma unroll
  for (int mf=0; mf<MF; mf++){
    #pragma unroll
    for (int nf=0; nf<NF; nf++){
      int row = m0 + wm + mf*16 + grp;
      int col = n0 + wn + nf*8 + tig*2;
      if (col < N){
        float2 v0 = make_float2(acc[mf][nf][0], acc[mf][nf][1]);
        float2 v1 = make_float2(acc[mf][nf][2], acc[mf][nf][3]);
        if (bias){
          float2 bv = *reinterpret_cast<const float2*>(bias + col);
          v0.x += bv.x; v0.y += bv.y;
          v1.x += bv.x; v1.y += bv.y;
        }
        if (ACT == 1){
          v0.x = gelu_exact(v0.x); v0.y = gelu_exact(v0.y);
          v1.x = gelu_exact(v1.x); v1.y = gelu_exact(v1.y);
        }
        *reinterpret_cast<float2*>(C + (size_t)row*ldc + col)     = v0;
        *reinterpret_cast<float2*>(C + (size_t)(row+8)*ldc + col) = v1;
      }
    }
  }
}

// ---------------- embeddings + LN --------------------------------------------
__global__ void embed_ln_kernel(const int* __restrict__ ids,
                                const float* __restrict__ we,
                                const float* __restrict__ pe,
                                const float* __restrict__ te,
                                const float* __restrict__ g,
                                const float* __restrict__ b)
{
  int t = blockIdx.x;
  int s = t & (SS-1);
  int id = ids[t];
  const float* wrow = we + (size_t)id*HH;
  const float* prow = pe + (size_t)s*HH;
  float x[3];
  float lsum = 0.f;
  #pragma unroll
  for (int i=0;i<3;i++){
    int c = threadIdx.x + i*256;
    x[i] = wrow[c] + prow[c] + te[c];
    lsum += x[i];
  }
  float mean = blockSum<8>(lsum) * (1.0f/HH);
  float ls2 = 0.f;
  #pragma unroll
  for (int i=0;i<3;i++){ x[i] -= mean; ls2 += x[i]*x[i]; }
  float var = blockSum<8>(ls2) * (1.0f/HH);
  float inv = rsqrtf(var + 1e-12f);
  #pragma unroll
  for (int i=0;i<3;i++){
    int c = threadIdx.x + i*256;
    g_h[(size_t)t*HH + c] = x[i]*inv*g[c] + b[c];
  }
}

// ---------------- residual + LN (in place on g_h) ----------------------------
__global__ void resln_kernel(const float* __restrict__ r,
                             const float* __restrict__ g,
                             const float* __restrict__ b)
{
  int t = blockIdx.x;
  float x[3];
  float lsum = 0.f;
  #pragma unroll
  for (int i=0;i<3;i++){
    int c = threadIdx.x + i*256;
    x[i] = g_h[(size_t)t*HH + c] + r[(size_t)t*HH + c];
    lsum += x[i];
  }
  float mean = blockSum<8>(lsum) * (1.0f/HH);
  float ls2 = 0.f;
  #pragma unroll
  for (int i=0;i<3;i++){ x[i] -= mean; ls2 += x[i]*x[i]; }
  float var = blockSum<8>(ls2) * (1.0f/HH);
  float inv = rsqrtf(var + 1e-12f);
  #pragma unroll
  for (int i=0;i<3;i++){
    int c = threadIdx.x + i*256;
    g_h[(size_t)t*HH + c] = x[i]*inv*g[c] + b[c];
  }
}

// ---------------- masked softmax over scores (in place) ----------------------
__global__ void softmax_kernel()
{
  int z = blockIdx.y;
  int s = blockIdx.x;
  float* row = g_scores + ((size_t)z*SS + s)*SS;
  float x[4];
  float mx = -3.4e38f;
  #pragma unroll
  for (int i=0;i<4;i++){
    int j = threadIdx.x + i*128;
    float v = row[j] * 0.125f;
    if (!(j < PLEN || j <= s)) v += -1e9f;
    x[i] = v;
    mx = fmaxf(mx, v);
  }
  mx = blockMax<4>(mx);
  float ls = 0.f;
  #pragma unroll
  for (int i=0;i<4;i++){ x[i] = __expf(x[i] - mx); ls += x[i]; }
  float sum = blockSum<4>(ls);
  float inv = 1.0f / sum;
  #pragma unroll
  for (int i=0;i<4;i++){
    int j = threadIdx.x + i*128;
    row[j] = x[i] * inv;
  }
}

// ---------------- cross entropy over valid rows ------------------------------
__global__ void zero_loss_kernel(){ g_loss_sum = 0.f; }

__global__ void ce_kernel(const int* __restrict__ labels)
{
  int r = blockIdx.x;
  int bb = r / NVALID_PER_B;
  int s  = PLEN + (r - bb*NVALID_PER_B);
  const float* row = g_logits + (size_t)r*VV;
  int lab = labels[bb*SS + s];

  float mx = -3.4e38f;
  for (int j = threadIdx.x; j < VV; j += 256) mx = fmaxf(mx, row[j]);
  mx = blockMax<8>(mx);
  float ls = 0.f;
  for (int j = threadIdx.x; j < VV; j += 256) ls += __expf(row[j] - mx);
  float sum = blockSum<8>(ls);
  if (threadIdx.x == 0){
    float nll = (logf(sum) + mx) - row[lab];
    atomicAdd(&g_loss_sum, nll);
  }
}

__global__ void finalize_kernel(float* out){
  out[0] = g_loss_sum * (1.0f/(float)NVALID);
}

// ---------------- host orchestration -----------------------------------------
template<int BN, bool TRANSB, int ACT>
static void launch_mm(const float* A, const float* B, const float* bias, float* C,
                      int M, int N, int K, int lda, int ldb, int ldc,
                      int batchInner,
                      long long sA1, long long sA2, long long sB1, long long sB2,
                      long long sC1, long long sC2, int gz)
{
  dim3 grid((N + BN - 1)/BN, M/128, gz);
  gemm_mma<BN,TRANSB,ACT><<<grid, 256>>>(
      A, B, bias, C, M, N, K, lda, ldb, ldc,
      batchInner, sA1, sA2, sB1, sB2, sC1, sC2);
}

extern "C" void kernel_launch(void* const* d_in, const int* in_sizes, int n_in,
                              void* d_out, int out_size)
{
  const int*   input_ids = (const int*)  d_in[0];
  const int*   labels    = (const int*)  d_in[1];
  const float* word_emb  = (const float*)d_in[2];
  const float* pos_emb   = (const float*)d_in[3];
  const float* type_emb  = (const float*)d_in[4];
  const float* eg        = (const float*)d_in[5];
  const float* eb        = (const float*)d_in[6];
  const float* Wq = (const float*)d_in[7];  const float* bq = (const float*)d_in[8];
  const float* Wk = (const float*)d_in[9];  const float* bk = (const float*)d_in[10];
  const float* Wv = (const float*)d_in[11]; const float* bv = (const float*)d_in[12];
  const float* Wo = (const float*)d_in[13]; const float* bo = (const float*)d_in[14];
  const float* ln1g = (const float*)d_in[15]; const float* ln1b = (const float*)d_in[16];
  const float* W1 = (const float*)d_in[17]; const float* bf1 = (const float*)d_in[18];
  const float* W2 = (const float*)d_in[19]; const float* bf2 = (const float*)d_in[20];
  const float* ln2g = (const float*)d_in[21]; const float* ln2b = (const float*)d_in[22];
  const float* Wc = (const float*)d_in[23]; const float* bc = (const float*)d_in[24];
  float* out = (float*)d_out;

  float *p_h, *p_q, *p_k, *p_v, *p_ctx, *p_tmp, *p_ffn, *p_sc, *p_lg;
  cudaGetSymbolAddress((void**)&p_h,   g_h);
  cudaGetSymbolAddress((void**)&p_q,   g_q);
  cudaGetSymbolAddress((void**)&p_k,   g_k);
  cudaGetSymbolAddress((void**)&p_v,   g_v);
  cudaGetSymbolAddress((void**)&p_ctx, g_ctx);
  cudaGetSymbolAddress((void**)&p_tmp, g_tmp);
  cudaGetSymbolAddress((void**)&p_ffn, g_ffn);
  cudaGetSymbolAddress((void**)&p_sc,  g_scores);
  cudaGetSymbolAddress((void**)&p_lg,  g_logits);

  zero_loss_kernel<<<1,1>>>();
  embed_ln_kernel<<<NTOK,256>>>(input_ids, word_emb, pos_emb, type_emb, eg, eb);

  const long long HDsq = (long long)HH*HH;
  const long long headStride = (long long)SS*HH;
  const long long scStrideH  = (long long)SS*SS;
  const long long scStrideB  = (long long)NHH*SS*SS;

  for (int l = 0; l < LL; l++) {
    const float* wq = Wq + (size_t)l*HDsq; const float* bql = bq + (size_t)l*HH;
    const float* wk = Wk + (size_t)l*HDsq; const float* bkl = bk + (size_t)l*HH;
    const float* wv = Wv + (size_t)l*HDsq; const float* bvl = bv + (size_t)l*HH;
    const float* wo = Wo + (size_t)l*HDsq; const float* bol = bo + (size_t)l*HH;
    const float* w1 = W1 + (size_t)l*HH*FFF; const float* b1l = bf1 + (size_t)l*FFF;
    const float* w2 = W2 + (size_t)l*FFF*HH; const float* b2l = bf2 + (size_t)l*HH;

    // QKV projections: [4096,768] @ [768,768] + b (NN)
    launch_mm<128,false,0>(p_h, wq, bql, p_q, NTOK, HH, HH, HH, HH, HH,
                           1, 0,0, 0,0, 0,0, 1);
    launch_mm<128,false,0>(p_h, wk, bkl, p_k, NTOK, HH, HH, HH, HH, HH,
                           1, 0,0, 0,0, 0,0, 1);
    launch_mm<128,false,0>(p_h, wv, bvl, p_v, NTOK, HH, HH, HH, HH, HH,
                           1, 0,0, 0,0, 0,0, 1);

    // scores = q @ k^T (NT), batched z = b*NH + h
    launch_mm<128,true,0>(p_q, p_k, nullptr, p_sc,
                          SS, SS, DHH, HH, HH, SS,
                          NHH,
                          headStride, (long long)DHH,
                          headStride, (long long)DHH,
                          scStrideB,  scStrideH, BB*NHH);

    softmax_kernel<<<dim3(SS, BB*NHH), 128>>>();

    // ctx = attn @ v (NN), M=512, N=64, K=512
    launch_mm<64,false,0>(p_sc, p_v, nullptr, p_ctx,
                          SS, DHH, SS, SS, HH, HH,
                          NHH,
                          scStrideB,  scStrideH,
                          headStride, (long long)DHH,
                          headStride, (long long)DHH, BB*NHH);

    // output proj + residual LN
    launch_mm<128,false,0>(p_ctx, wo, bol, p_tmp, NTOK, HH, HH, HH, HH, HH,
                           1, 0,0, 0,0, 0,0, 1);
    resln_kernel<<<NTOK,256>>>(p_tmp, ln1g + (size_t)l*HH, ln1b + (size_t)l*HH);

    // FFN
    launch_mm<128,false,1>(p_h, w1, b1l, p_ffn, NTOK, FFF, HH, HH, FFF, FFF,
                           1, 0,0, 0,0, 0,0, 1);   // fused GELU
    launch_mm<128,false,0>(p_ffn, w2, b2l, p_tmp, NTOK, HH, FFF, FFF, HH, HH,
                           1, 0,0, 0,0, 0,0, 1);
    resln_kernel<<<NTOK,256>>>(p_tmp, ln2g + (size_t)l*HH, ln2b + (size_t)l*HH);
  }

  // logits for valid tokens only (rows s in [128,512) per batch, contiguous)
  launch_mm<128,false,0>(p_h + (size_t)PLEN*HH, Wc, bc, p_lg,
                         NVALID_PER_B, VV, HH, HH, VV, VV,
                         1,
                         (long long)SS*HH, 0,
                         0, 0,
                         (long long)NVALID_PER_B*VV, 0, BB);

  ce_kernel<<<NVALID,256>>>(labels);
  finalize_kernel<<<1,1>>>(out);
}

// round 8
// speedup vs baseline: 3.2801x; 1.1782x over previous
#include <cuda_runtime.h>
#include <cuda_bf16.h>
#include <cstdint>
#include <math.h>

// Problem constants
#define BB 8
#define SS 512
#define HH 768
#define NHH 12
#define DHH 64
#define LL 12
#define VV 21128
#define FFF 3072
#define PLEN 128
#define NTOK (BB*SS)
#define NVALID_PER_B (SS-PLEN)
#define NVALID (BB*NVALID_PER_B)
#define QKVW (3*HH)            // 2304

// ---------------- scratch (device globals; no allocations allowed) ----------
__device__ float g_h[NTOK*HH];
__device__ float g_qkv[(size_t)NTOK*QKVW];
__device__ float g_ctx[NTOK*HH];
__device__ float g_tmp[NTOK*HH];
__device__ float g_ffn[NTOK*FFF];
__device__ float g_scores[(size_t)BB*NHH*SS*SS];
__device__ float g_logits[(size_t)NVALID*VV];
__device__ float g_wqkv[(size_t)LL*HH*QKVW];
__device__ float g_bqkv[(size_t)LL*QKVW];
__device__ float g_loss_sum;

// ---------------- helpers ----------------------------------------------------
__device__ __forceinline__ float warpSum(float v){
  #pragma unroll
  for (int o=16;o;o>>=1) v += __shfl_xor_sync(0xffffffffu, v, o);
  return v;
}
__device__ __forceinline__ float warpMax(float v){
  #pragma unroll
  for (int o=16;o;o>>=1) v = fmaxf(v, __shfl_xor_sync(0xffffffffu, v, o));
  return v;
}
template<int NW>
__device__ __forceinline__ float blockSum(float v){
  __shared__ float sh[NW];
  __syncthreads();
  v = warpSum(v);
  if ((threadIdx.x & 31)==0) sh[threadIdx.x>>5] = v;
  __syncthreads();
  float r = 0.f;
  #pragma unroll
  for (int i=0;i<NW;i++) r += sh[i];
  return r;
}
template<int NW>
__device__ __forceinline__ float blockMax(float v){
  __shared__ float sh[NW];
  __syncthreads();
  v = warpMax(v);
  if ((threadIdx.x & 31)==0) sh[threadIdx.x>>5] = v;
  __syncthreads();
  float r = -3.4e38f;
  #pragma unroll
  for (int i=0;i<NW;i++) r = fmaxf(r, sh[i]);
  return r;
}
__device__ __forceinline__ float gelu_exact(float x){
  return 0.5f * x * (1.0f + erff(x * 0.70710678118654752f));
}

__device__ __forceinline__ uint32_t smem_u32(const void* p){
  uint32_t a;
  asm("{ .reg .u64 t; cvta.to.shared.u64 t, %1; cvt.u32.u64 %0, t; }" : "=r"(a) : "l"(p));
  return a;
}

// split a pair of fp32 into packed bf16 hi and packed bf16 lo (x0 -> low half)
__device__ __forceinline__ void split_bf16_pair(float x0, float x1,
                                                uint32_t& hi, uint32_t& lo){
  uint32_t h;
  asm("cvt.rn.bf16x2.f32 %0, %1, %2;" : "=r"(h) : "f"(x1), "f"(x0));
  float h0 = __uint_as_float(h << 16);
  float h1 = __uint_as_float(h & 0xffff0000u);
  float l0 = x0 - h0;
  float l1 = x1 - h1;
  asm("cvt.rn.bf16x2.f32 %0, %1, %2;" : "=r"(lo) : "f"(l1), "f"(l0));
  hi = h;
}

__device__ __forceinline__ void mma_bf16(float* d, const uint32_t* a, const uint32_t* b){
  asm volatile(
    "mma.sync.aligned.m16n8k16.row.col.f32.bf16.bf16.f32 "
    "{%0,%1,%2,%3}, {%4,%5,%6,%7}, {%8,%9}, {%0,%1,%2,%3};\n"
    : "+f"(d[0]), "+f"(d[1]), "+f"(d[2]), "+f"(d[3])
    : "r"(a[0]), "r"(a[1]), "r"(a[2]), "r"(a[3]), "r"(b[0]), "r"(b[1]));
}
__device__ __forceinline__ void ldsm_x4(uint32_t* r, uint32_t addr){
  asm volatile("ldmatrix.sync.aligned.m8n8.x4.shared.b16 {%0,%1,%2,%3}, [%4];"
    : "=r"(r[0]), "=r"(r[1]), "=r"(r[2]), "=r"(r[3]) : "r"(addr));
}
__device__ __forceinline__ void ldsm_x4_t(uint32_t* r, uint32_t addr){
  asm volatile("ldmatrix.sync.aligned.m8n8.x4.trans.shared.b16 {%0,%1,%2,%3}, [%4];"
    : "=r"(r[0]), "=r"(r[1]), "=r"(r[2]), "=r"(r[3]) : "r"(addr));
}

// ---------------- 3xBF16 mma.sync GEMM, BN=64 tiles, 2 CTAs/SM ---------------
// C[M,N] = A[M,K] @ op(B) (+bias)(+GELU). TRANSB: B is [N,K] (NT, C=A@B^T);
// else B is [K,N] (NN). BM=128, BK=16, warp tile 32x32 (8 warps), single
// __syncthreads per chunk, register-prefetch double buffering,
// pre-split bf16 hi/lo smem + ldmatrix fragments.

template<int BN, bool TRANSB, int ACT>
__global__ __launch_bounds__(256,2) void gemm_mma(
    const float* __restrict__ Ag, const float* __restrict__ Bg,
    const float* __restrict__ bias, float* __restrict__ Cg,
    int M, int N, int K, int lda, int ldb, int ldc,
    int batchInner,
    long long sA1, long long sA2, long long sB1, long long sB2,
    long long sC1, long long sC2)
{
  constexpr int BM = 128;
  constexpr int BK = 16;
  constexpr int WARPS_N = BN/32;         // 2
  constexpr int WARPS_M = 8/WARPS_N;     // 4
  constexpr int WM = BM / WARPS_M;       // 32
  constexpr int WN = BN / WARPS_N;       // 32
  constexpr int MF = WM / 16;            // 2
  constexpr int NF = WN / 8;             // 4

  constexpr int AP = 24;                            // 48B rows: 16B-aligned, conflict-free
  constexpr int BROWS = TRANSB ? BN : BK;
  constexpr int BP = TRANSB ? 24 : (BN + 8);        // 48B / 144B rows

  __shared__ __align__(16) __nv_bfloat16 Ah[2][BM][AP];
  __shared__ __align__(16) __nv_bfloat16 Al[2][BM][AP];
  __shared__ __align__(16) __nv_bfloat16 Bh[2][BROWS][BP];
  __shared__ __align__(16) __nv_bfloat16 Bl[2][BROWS][BP];

  const int tid  = threadIdx.x;
  const int wid  = tid >> 5;
  const int lane = tid & 31;
  const int grp  = lane >> 2;
  const int tig  = lane & 3;

  const int z  = blockIdx.z;
  const int zo = z / batchInner;
  const int zi = z - zo * batchInner;
  const float* A  = Ag + zo*sA1 + zi*sA2;
  const float* Bp = Bg + zo*sB1 + zi*sB2;
  float*       C  = Cg + zo*sC1 + zi*sC2;

  const int m0 = blockIdx.y * BM;
  const int n0 = blockIdx.x * BN;
  const int wm = (wid / WARPS_N) * WM;
  const int wn = (wid % WARPS_N) * WN;

  float acc[MF][NF][4];
  #pragma unroll
  for (int i=0;i<MF;i++)
    #pragma unroll
    for (int j=0;j<NF;j++)
      #pragma unroll
      for (int r=0;r<4;r++) acc[i][j][r] = 0.f;

  const int nch = K / BK;

  // register staging for global tiles
  float4 aReg[2];
  constexpr int NB4 = TRANSB ? 1 : (BK*BN/4/256);   // float4 per thread (1)
  float4 bReg[NB4];

  const int aRow0 = tid >> 2;            // 0..63 (i=0), +64 (i=1)
  const int aKg   = tid & 3;
  const int btN   = tid >> 2;            // NT: 0..63 row
  const int btK   = (tid & 3) * 4;       // NT: k offset

  auto ldgA = [&](int c){
    int k0 = c * BK;
    #pragma unroll
    for (int i=0;i<2;i++){
      int row = aRow0 + i*64;
      aReg[i] = *reinterpret_cast<const float4*>(A + (size_t)(m0+row)*lda + k0 + aKg*4);
    }
  };
  auto stsA = [&](int buf){
    #pragma unroll
    for (int i=0;i<2;i++){
      int row = aRow0 + i*64;
      uint32_t h0,l0,h1,l1;
      split_bf16_pair(aReg[i].x, aReg[i].y, h0, l0);
      split_bf16_pair(aReg[i].z, aReg[i].w, h1, l1);
      *reinterpret_cast<uint2*>(&Ah[buf][row][aKg*4]) = make_uint2(h0,h1);
      *reinterpret_cast<uint2*>(&Al[buf][row][aKg*4]) = make_uint2(l0,l1);
    }
  };

  auto ldgB = [&](int c){
    int k0 = c * BK;
    if (TRANSB){
      bReg[0] = *reinterpret_cast<const float4*>(Bp + (size_t)(n0+btN)*ldb + k0 + btK);
    } else {
      #pragma unroll
      for (int i=0;i<NB4;i++){
        int idx = i*256 + tid;
        int k  = idx / (BN/4);
        int ng = idx % (BN/4);
        int gn = n0 + ng*4;
        if (gn < N)
          bReg[i] = *reinterpret_cast<const float4*>(Bp + (size_t)(k0+k)*ldb + gn);
        else
          bReg[i] = make_float4(0.f,0.f,0.f,0.f);
      }
    }
  };
  auto stsB = [&](int buf){
    if (TRANSB){
      uint32_t h0,l0,h1,l1;
      split_bf16_pair(bReg[0].x, bReg[0].y, h0, l0);
      split_bf16_pair(bReg[0].z, bReg[0].w, h1, l1);
      *reinterpret_cast<uint2*>(&Bh[buf][btN][btK]) = make_uint2(h0,h1);
      *reinterpret_cast<uint2*>(&Bl[buf][btN][btK]) = make_uint2(l0,l1);
    } else {
      #pragma unroll
      for (int i=0;i<NB4;i++){
        int idx = i*256 + tid;
        int k  = idx / (BN/4);
        int ng = idx % (BN/4);
        uint32_t h0,l0,h1,l1;
        split_bf16_pair(bReg[i].x, bReg[i].y, h0, l0);
        split_bf16_pair(bReg[i].z, bReg[i].w, h1, l1);
        *reinterpret_cast<uint2*>(&Bh[buf][k][ng*4]) = make_uint2(h0,h1);
        *reinterpret_cast<uint2*>(&Bl[buf][k][ng*4]) = make_uint2(l0,l1);
      }
    }
  };

  // ldmatrix lane decodes
  const int lrow = lane & 7;
  const int lsel = (lane >> 3) & 1;
  const int lhi  = lane >> 4;

  // ---- prologue ----
  ldgA(0); ldgB(0);
  stsA(0); stsB(0);
  __syncthreads();

  for (int c = 0; c < nch; c++){
    const int buf = c & 1;
    if (c+1 < nch){ ldgA(c+1); ldgB(c+1); }

    // ---- fragment loads via ldmatrix (from buf) ----
    uint32_t ah[MF][4], al[MF][4];
    #pragma unroll
    for (int mf=0; mf<MF; mf++){
      int r = wm + mf*16 + lsel*8 + lrow;
      ldsm_x4(ah[mf], smem_u32(&Ah[buf][r][lhi*8]));
      ldsm_x4(al[mf], smem_u32(&Al[buf][r][lhi*8]));
    }
    uint32_t bh[NF][2], bl[NF][2];
    #pragma unroll
    for (int nfp=0; nfp<NF/2; nfp++){
      int nb = wn + nfp*16;
      uint32_t rh[4], rl[4];
      if (TRANSB){
        int r = nb + lhi*8 + lrow;
        ldsm_x4(rh, smem_u32(&Bh[buf][r][lsel*8]));
        ldsm_x4(rl, smem_u32(&Bl[buf][r][lsel*8]));
      } else {
        int r = lsel*8 + lrow;
        ldsm_x4_t(rh, smem_u32(&Bh[buf][r][nb + lhi*8]));
        ldsm_x4_t(rl, smem_u32(&Bl[buf][r][nb + lhi*8]));
      }
      bh[2*nfp][0]=rh[0]; bh[2*nfp][1]=rh[1]; bh[2*nfp+1][0]=rh[2]; bh[2*nfp+1][1]=rh[3];
      bl[2*nfp][0]=rl[0]; bl[2*nfp][1]=rl[1]; bl[2*nfp+1][0]=rl[2]; bl[2*nfp+1][1]=rl[3];
    }

    #pragma unroll
    for (int mf=0; mf<MF; mf++)
      #pragma unroll
      for (int nf=0; nf<NF; nf++){
        mma_bf16(acc[mf][nf], ah[mf], bh[nf]);
        mma_bf16(acc[mf][nf], al[mf], bh[nf]);
        mma_bf16(acc[mf][nf], ah[mf], bl[nf]);
      }

    // store NEXT tile into the other buffer; single sync per chunk.
    // (STS targets buf^1, whose last readers were separated by the previous
    //  iteration's sync; ldmatrix above reads buf — no hazard.)
    if (c+1 < nch){
      stsA(buf^1); stsB(buf^1);
    }
    __syncthreads();
  }

  // ---- epilogue ----
  #pragma unroll
  for (int mf=0; mf<MF; mf++){
    #pragma unroll
    for (int nf=0; nf<NF; nf++){
      int row = m0 + wm + mf*16 + grp;
      int col = n0 + wn + nf*8 + tig*2;
      if (col < N){
        float2 v0 = make_float2(acc[mf][nf][0], acc[mf][nf][1]);
        float2 v1 = make_float2(acc[mf][nf][2], acc[mf][nf][3]);
        if (bias){
          float2 bv = *reinterpret_cast<const float2*>(bias + col);
          v0.x += bv.x; v0.y += bv.y;
          v1.x += bv.x; v1.y += bv.y;
        }
        if (ACT == 1){
          v0.x = gelu_exact(v0.x); v0.y = gelu_exact(v0.y);
          v1.x = gelu_exact(v1.x); v1.y = gelu_exact(v1.y);
        }
        *reinterpret_cast<float2*>(C + (size_t)row*ldc + col)     = v0;
        *reinterpret_cast<float2*>(C + (size_t)(row+8)*ldc + col) = v1;
      }
    }
  }
}

// ---------------- QKV weight/bias packing ------------------------------------
__global__ void pack_qkv_kernel(const float* __restrict__ Wq,
                                const float* __restrict__ Wk,
                                const float* __restrict__ Wv,
                                const float* __restrict__ bq,
                                const float* __restrict__ bk,
                                const float* __restrict__ bv)
{
  const size_t total = (size_t)LL*HH*QKVW;
  for (size_t idx = (size_t)blockIdx.x*blockDim.x + threadIdx.x;
       idx < total; idx += (size_t)gridDim.x*blockDim.x){
    int col = (int)(idx % QKVW);
    size_t rl = idx / QKVW;            // l*HH + row
    float v;
    if (col < HH)        v = Wq[rl*HH + col];
    else if (col < 2*HH) v = Wk[rl*HH + col - HH];
    else                 v = Wv[rl*HH + col - 2*HH];
    g_wqkv[idx] = v;
  }
  for (size_t idx = (size_t)blockIdx.x*blockDim.x + threadIdx.x;
       idx < (size_t)LL*QKVW; idx += (size_t)gridDim.x*blockDim.x){
    int col = (int)(idx % QKVW);
    int l   = (int)(idx / QKVW);
    float v;
    if (col < HH)        v = bq[l*HH + col];
    else if (col < 2*HH) v = bk[l*HH + col - HH];
    else                 v = bv[l*HH + col - 2*HH];
    g_bqkv[idx] = v;
  }
}

// ---------------- embeddings + LN --------------------------------------------
__global__ void embed_ln_kernel(const int* __restrict__ ids,
                                const float* __restrict__ we,
                                const float* __restrict__ pe,
                                const float* __restrict__ te,
                                const float* __restrict__ g,
                                const float* __restrict__ b)
{
  int t = blockIdx.x;
  int s = t & (SS-1);
  int id = ids[t];
  const float* wrow = we + (size_t)id*HH;
  const float* prow = pe + (size_t)s*HH;
  float x[3];
  float lsum = 0.f;
  #pragma unroll
  for (int i=0;i<3;i++){
    int c = threadIdx.x + i*256;
    x[i] = wrow[c] + prow[c] + te[c];
    lsum += x[i];
  }
  float mean = blockSum<8>(lsum) * (1.0f/HH);
  float ls2 = 0.f;
  #pragma unroll
  for (int i=0;i<3;i++){ x[i] -= mean; ls2 += x[i]*x[i]; }
  float var = blockSum<8>(ls2) * (1.0f/HH);
  float inv = rsqrtf(var + 1e-12f);
  #pragma unroll
  for (int i=0;i<3;i++){
    int c = threadIdx.x + i*256;
    g_h[(size_t)t*HH + c] = x[i]*inv*g[c] + b[c];
  }
}

// ---------------- residual + LN (in place on g_h) ----------------------------
__global__ void resln_kernel(const float* __restrict__ r,
                             const float* __restrict__ g,
                             const float* __restrict__ b)
{
  int t = blockIdx.x;
  float x[3];
  float lsum = 0.f;
  #pragma unroll
  for (int i=0;i<3;i++){
    int c = threadIdx.x + i*256;
    x[i] = g_h[(size_t)t*HH + c] + r[(size_t)t*HH + c];
    lsum += x[i];
  }
  float mean = blockSum<8>(lsum) * (1.0f/HH);
  float ls2 = 0.f;
  #pragma unroll
  for (int i=0;i<3;i++){ x[i] -= mean; ls2 += x[i]*x[i]; }
  float var = blockSum<8>(ls2) * (1.0f/HH);
  float inv = rsqrtf(var + 1e-12f);
  #pragma unroll
  for (int i=0;i<3;i++){
    int c = threadIdx.x + i*256;
    g_h[(size_t)t*HH + c] = x[i]*inv*g[c] + b[c];
  }
}

// ---------------- masked softmax over scores (in place) ----------------------
__global__ void softmax_kernel()
{
  int z = blockIdx.y;
  int s = blockIdx.x;
  float* row = g_scores + ((size_t)z*SS + s)*SS;
  float x[4];
  float mx = -3.4e38f;
  #pragma unroll
  for (int i=0;i<4;i++){
    int j = threadIdx.x + i*128;
    float v = row[j] * 0.125f;
    if (!(j < PLEN || j <= s)) v += -1e9f;
    x[i] = v;
    mx = fmaxf(mx, v);
  }
  mx = blockMax<4>(mx);
  float ls = 0.f;
  #pragma unroll
  for (int i=0;i<4;i++){ x[i] = __expf(x[i] - mx); ls += x[i]; }
  float sum = blockSum<4>(ls);
  float inv = 1.0f / sum;
  #pragma unroll
  for (int i=0;i<4;i++){
    int j = threadIdx.x + i*128;
    row[j] = x[i] * inv;
  }
}

// ---------------- cross entropy over valid rows ------------------------------
__global__ void zero_loss_kernel(){ g_loss_sum = 0.f; }

__global__ void ce_kernel(const int* __restrict__ labels)
{
  int r = blockIdx.x;
  int bb = r / NVALID_PER_B;
  int s  = PLEN + (r - bb*NVALID_PER_B);
  const float* row = g_logits + (size_t)r*VV;
  int lab = labels[bb*SS + s];

  float mx = -3.4e38f;
  for (int j = threadIdx.x; j < VV; j += 256) mx = fmaxf(mx, row[j]);
  mx = blockMax<8>(mx);
  float ls = 0.f;
  for (int j = threadIdx.x; j < VV; j += 256) ls += __expf(row[j] - mx);
  float sum = blockSum<8>(ls);
  if (threadIdx.x == 0){
    float nll = (logf(sum) + mx) - row[lab];
    atomicAdd(&g_loss_sum, nll);
  }
}

__global__ void finalize_kernel(float* out){
  out[0] = g_loss_sum * (1.0f/(float)NVALID);
}

// ---------------- host orchestration -----------------------------------------
template<int BN, bool TRANSB, int ACT>
static void launch_mm(const float* A, const float* B, const float* bias, float* C,
                      int M, int N, int K, int lda, int ldb, int ldc,
                      int batchInner,
                      long long sA1, long long sA2, long long sB1, long long sB2,
                      long long sC1, long long sC2, int gz)
{
  dim3 grid((N + BN - 1)/BN, M/128, gz);
  gemm_mma<BN,TRANSB,ACT><<<grid, 256>>>(
      A, B, bias, C, M, N, K, lda, ldb, ldc,
      batchInner, sA1, sA2, sB1, sB2, sC1, sC2);
}

extern "C" void kernel_launch(void* const* d_in, const int* in_sizes, int n_in,
                              void* d_out, int out_size)
{
  const int*   input_ids = (const int*)  d_in[0];
  const int*   labels    = (const int*)  d_in[1];
  const float* word_emb  = (const float*)d_in[2];
  const float* pos_emb   = (const float*)d_in[3];
  const float* type_emb  = (const float*)d_in[4];
  const float* eg        = (const float*)d_in[5];
  const float* eb        = (const float*)d_in[6];
  const float* Wq = (const float*)d_in[7];  const float* bq = (const float*)d_in[8];
  const float* Wk = (const float*)d_in[9];  const float* bk = (const float*)d_in[10];
  const float* Wv = (const float*)d_in[11]; const float* bv = (const float*)d_in[12];
  const float* Wo = (const float*)d_in[13]; const float* bo = (const float*)d_in[14];
  const float* ln1g = (const float*)d_in[15]; const float* ln1b = (const float*)d_in[16];
  const float* W1 = (const float*)d_in[17]; const float* bf1 = (const float*)d_in[18];
  const float* W2 = (const float*)d_in[19]; const float* bf2 = (const float*)d_in[20];
  const float* ln2g = (const float*)d_in[21]; const float* ln2b = (const float*)d_in[22];
  const float* Wc = (const float*)d_in[23]; const float* bc = (const float*)d_in[24];
  float* out = (float*)d_out;

  float *p_h, *p_qkv, *p_ctx, *p_tmp, *p_ffn, *p_sc, *p_lg, *p_wqkv, *p_bqkv;
  cudaGetSymbolAddress((void**)&p_h,    g_h);
  cudaGetSymbolAddress((void**)&p_qkv,  g_qkv);
  cudaGetSymbolAddress((void**)&p_ctx,  g_ctx);
  cudaGetSymbolAddress((void**)&p_tmp,  g_tmp);
  cudaGetSymbolAddress((void**)&p_ffn,  g_ffn);
  cudaGetSymbolAddress((void**)&p_sc,   g_scores);
  cudaGetSymbolAddress((void**)&p_lg,   g_logits);
  cudaGetSymbolAddress((void**)&p_wqkv, g_wqkv);
  cudaGetSymbolAddress((void**)&p_bqkv, g_bqkv);

  zero_loss_kernel<<<1,1>>>();
  pack_qkv_kernel<<<1024,256>>>(Wq, Wk, Wv, bq, bk, bv);
  embed_ln_kernel<<<NTOK,256>>>(input_ids, word_emb, pos_emb, type_emb, eg, eb);

  const long long HDsq = (long long)HH*HH;
  const long long headStride = (long long)SS*HH;
  const long long qkvBatch   = (long long)SS*QKVW;
  const long long scStrideH  = (long long)SS*SS;
  const long long scStrideB  = (long long)NHH*SS*SS;

  for (int l = 0; l < LL; l++) {
    const float* wo = Wo + (size_t)l*HDsq; const float* bol = bo + (size_t)l*HH;
    const float* w1 = W1 + (size_t)l*HH*FFF; const float* b1l = bf1 + (size_t)l*FFF;
    const float* w2 = W2 + (size_t)l*FFF*HH; const float* b2l = bf2 + (size_t)l*HH;

    // fused QKV projection: [4096,768] @ [768,2304] + b (NN)
    launch_mm<64,false,0>(p_h, p_wqkv + (size_t)l*HH*QKVW, p_bqkv + (size_t)l*QKVW,
                          p_qkv, NTOK, QKVW, HH, HH, QKVW, QKVW,
                          1, 0,0, 0,0, 0,0, 1);

    // scores = q @ k^T (NT), batched z = b*NH + h; q,k inside g_qkv
    launch_mm<64,true,0>(p_qkv, p_qkv + HH, nullptr, p_sc,
                         SS, SS, DHH, QKVW, QKVW, SS,
                         NHH,
                         qkvBatch, (long long)DHH,
                         qkvBatch, (long long)DHH,
                         scStrideB, scStrideH, BB*NHH);

    softmax_kernel<<<dim3(SS, BB*NHH), 128>>>();

    // ctx = attn @ v (NN), M=512, N=64, K=512; v inside g_qkv
    launch_mm<64,false,0>(p_sc, p_qkv + 2*HH, nullptr, p_ctx,
                          SS, DHH, SS, SS, QKVW, HH,
                          NHH,
                          scStrideB, scStrideH,
                          qkvBatch, (long long)DHH,
                          headStride, (long long)DHH, BB*NHH);

    // output proj + residual LN
    launch_mm<64,false,0>(p_ctx, wo, bol, p_tmp, NTOK, HH, HH, HH, HH, HH,
                          1, 0,0, 0,0, 0,0, 1);
    resln_kernel<<<NTOK,256>>>(p_tmp, ln1g + (size_t)l*HH, ln1b + (size_t)l*HH);

    // FFN
    launch_mm<64,false,1>(p_h, w1, b1l, p_ffn, NTOK, FFF, HH, HH, FFF, FFF,
                          1, 0,0, 0,0, 0,0, 1);   // fused GELU
    launch_mm<64,false,0>(p_ffn, w2, b2l, p_tmp, NTOK, HH, FFF, FFF, HH, HH,
                          1, 0,0, 0,0, 0,0, 1);
    resln_kernel<<<NTOK,256>>>(p_tmp, ln2g + (size_t)l*HH, ln2b + (size_t)l*HH);
  }

  // logits for valid tokens only (rows s in [128,512) per batch, contiguous)
  launch_mm<64,false,0>(p_h + (size_t)PLEN*HH, Wc, bc, p_lg,
                        NVALID_PER_B, VV, HH, HH, VV, VV,
                        1,
                        (long long)SS*HH, 0,
                        0, 0,
                        (long long)NVALID_PER_B*VV, 0, BB);

  ce_kernel<<<NVALID,256>>>(labels);
  finalize_kernel<<<1,1>>>(out);
}